// round 1
// baseline (speedup 1.0000x reference)
#include <cuda_runtime.h>
#include <math.h>

#define BATCH 16
#define DIMK  1024
#define TT    2048
#define NFFT  1024
#define HOP   256
#define NBINS 513
#define NBP   520            // padded row stride for mag/phase
#define MTOT  (BATCH * TT)   // 32768
#define OUTLEN (HOP * (TT - 1))  // 524032

// ---------------- scratch (static device globals; no allocation) -------------
__device__ float g_mag[(size_t)MTOT * NBP];
__device__ float g_frq[(size_t)MTOT * NBP];      // inst_freq, overwritten by phase
__device__ float g_frames[(size_t)MTOT * NFFT];
__device__ float g_twr[512];
__device__ float g_twi[512];
__device__ float g_win[1024];
__device__ float g_win2[1024];

// ---------------- table init -------------------------------------------------
__global__ void init_tables() {
    int i = blockIdx.x * blockDim.x + threadIdx.x;
    const float TWO_PI = 6.283185307179586f;
    if (i < 512) {
        float ang = TWO_PI * (float)i / 1024.0f;
        g_twr[i] = cosf(ang);
        g_twi[i] = sinf(ang);   // + sign: inverse FFT twiddles
    }
    if (i < 1024) {
        float w = 0.5f * (1.0f - cosf(TWO_PI * (float)i / 1024.0f));
        g_win[i]  = w;
        g_win2[i] = w * w;
    }
}

// ---------------- fused dual GEMM (mag + phase heads) -------------------------
// A[m][k] = x[b][k][t], m = b*2048 + t  (t contiguous -> coalesced per k-row)
// virtual B rows: n<513 -> W_mag[n], else W_phase[n-513]
#define BM 128
#define BN 64
#define BK 16

__global__ __launch_bounds__(256) void gemm_kernel(
    const float* __restrict__ x,
    const float* __restrict__ Wm, const float* __restrict__ bm,
    const float* __restrict__ Wp, const float* __restrict__ bp)
{
    __shared__ float As[BK][BM];
    __shared__ float Bs[BK][BN + 4];   // pad to avoid write conflicts, keep 16B align

    int tid = threadIdx.x;
    int n0 = blockIdx.x * BN;          // n-tile fastest -> A reused via L2
    int m0 = blockIdx.y * BM;
    int b  = m0 >> 11;                 // BM divides T, so one batch per block
    int t0 = m0 & (TT - 1);
    const float* xb = x + (size_t)b * DIMK * TT + t0;

    int tx = tid & 15;                 // 16 x 16 thread grid
    int ty = tid >> 4;

    float acc[8][4];
    #pragma unroll
    for (int i = 0; i < 8; i++)
        #pragma unroll
        for (int j = 0; j < 4; j++) acc[i][j] = 0.f;

    // B load lanes: 4 threads per virtual row, float4 of K each
    int jb = tid >> 2;                 // 0..63 (row within tile)
    int qb = tid & 3;                  // 0..3  (k quarter)
    int ng = n0 + jb;
    const float* wrow = nullptr;
    if (ng < NBINS)            wrow = Wm + (size_t)ng * DIMK;
    else if (ng < 2 * NBINS)   wrow = Wp + (size_t)(ng - NBINS) * DIMK;

    for (int k0 = 0; k0 < DIMK; k0 += BK) {
        // A tile: 128x16 floats, float4 x2 per thread, coalesced over t
        #pragma unroll
        for (int r = 0; r < 2; r++) {
            int idx = r * 256 + tid;
            int kk  = idx >> 5;
            int mq  = (idx & 31) << 2;
            float4 v = *reinterpret_cast<const float4*>(
                xb + (size_t)(k0 + kk) * TT + mq);
            *reinterpret_cast<float4*>(&As[kk][mq]) = v;
        }
        // B tile: 64x16 floats, one float4 per thread
        {
            float4 v = make_float4(0.f, 0.f, 0.f, 0.f);
            if (wrow) v = *reinterpret_cast<const float4*>(wrow + k0 + qb * 4);
            Bs[qb * 4 + 0][jb] = v.x;
            Bs[qb * 4 + 1][jb] = v.y;
            Bs[qb * 4 + 2][jb] = v.z;
            Bs[qb * 4 + 3][jb] = v.w;
        }
        __syncthreads();

        #pragma unroll
        for (int kk = 0; kk < BK; kk++) {
            float4 a0 = *reinterpret_cast<const float4*>(&As[kk][ty * 8]);
            float4 a1 = *reinterpret_cast<const float4*>(&As[kk][ty * 8 + 4]);
            float4 bv = *reinterpret_cast<const float4*>(&Bs[kk][tx * 4]);
            float av[8] = {a0.x, a0.y, a0.z, a0.w, a1.x, a1.y, a1.z, a1.w};
            float bw[4] = {bv.x, bv.y, bv.z, bv.w};
            #pragma unroll
            for (int i = 0; i < 8; i++)
                #pragma unroll
                for (int j = 0; j < 4; j++)
                    acc[i][j] = fmaf(av[i], bw[j], acc[i][j]);
        }
        __syncthreads();
    }

    const float PI_F = 3.14159265358979323846f;
    #pragma unroll
    for (int i = 0; i < 8; i++) {
        int m = m0 + ty * 8 + i;
        size_t row = (size_t)m * NBP;
        #pragma unroll
        for (int j = 0; j < 4; j++) {
            int n = n0 + tx * 4 + j;
            if (n < NBINS) {
                float v = acc[i][j] + bm[n];
                v = fminf(fmaxf(v, -10.f), 10.f);
                g_mag[row + n] = expf(v);
            } else if (n < 2 * NBINS) {
                int nn = n - NBINS;
                float v = acc[i][j] + bp[nn];
                v = fminf(fmaxf(v, -PI_F), PI_F);
                g_frq[row + nn] = v;
            }
        }
    }
}

// ---------------- cumsum along time (in place) --------------------------------
__global__ void cumsum_kernel() {
    int n = blockIdx.x * 128 + threadIdx.x;
    int b = blockIdx.y;
    if (n >= NBINS) return;
    size_t base = (size_t)b * TT * NBP + n;
    float acc = 0.f;
    #pragma unroll 8
    for (int t = 0; t < TT; t++) {
        size_t off = base + (size_t)t * NBP;
        acc += g_frq[off];
        g_frq[off] = acc;
    }
}

// ---------------- per-frame irfft(1024) + window -------------------------------
__global__ __launch_bounds__(256) void frames_kernel() {
    __shared__ float sre[513];
    __shared__ float sim[513];
    __shared__ float wre[1024];
    __shared__ float wim[1024];

    int f = blockIdx.x;                // frame = b*T + t
    int tid = threadIdx.x;
    size_t base = (size_t)f * NBP;

    // build half-spectrum: mag * exp(i*phase)
    for (int n = tid; n < 513; n += 256) {
        float mg = g_mag[base + n];
        float ph = g_frq[base + n];
        float s, c;
        sincosf(ph, &s, &c);
        sre[n] = mg * c;
        sim[n] = mg * s;
    }
    __syncthreads();

    // bit-reversed Hermitian fill
    for (int k = tid; k < 1024; k += 256) {
        int j = __brev((unsigned)k) >> 22;
        if (j <= 512) {
            wre[k] = sre[j];
            wim[k] = sim[j];
        } else {
            int src = 1024 - j;
            wre[k] = sre[src];
            wim[k] = -sim[src];
        }
    }
    __syncthreads();

    // 10-stage radix-2 inverse FFT (DIT), 512 butterflies/stage, 2 per thread
    #pragma unroll
    for (int s = 1; s <= 10; s++) {
        int half = 1 << (s - 1);
        #pragma unroll 2
        for (int u = tid; u < 512; u += 256) {
            int i = ((u >> (s - 1)) << s) | (u & (half - 1));
            int twix = (u & (half - 1)) << (10 - s);
            float wr = g_twr[twix], wi = g_twi[twix];
            float ar = wre[i],       ai = wim[i];
            float br = wre[i + half], bi = wim[i + half];
            float tr = br * wr - bi * wi;
            float ti = br * wi + bi * wr;
            wre[i]        = ar + tr;
            wim[i]        = ai + ti;
            wre[i + half] = ar - tr;
            wim[i + half] = ai - ti;
        }
        __syncthreads();
    }

    // real part * (1/N) * window
    size_t ob = (size_t)f * NFFT;
    const float inv_n = 1.0f / 1024.0f;
    for (int k = tid; k < 1024; k += 256)
        g_frames[ob + k] = wre[k] * inv_n * g_win[k];
}

// ---------------- overlap-add (gather), envelope, trim, clip -------------------
__global__ void oa_kernel(float* __restrict__ out) {
    int idx = blockIdx.x * 256 + threadIdx.x;
    if (idx >= BATCH * OUTLEN) return;
    int b = idx / OUTLEN;
    int s = idx - b * OUTLEN;
    int p = s + NFFT / 2;

    int t1 = p >> 8;  if (t1 > TT - 1) t1 = TT - 1;
    int t0 = (p >= NFFT - HOP) ? ((p - (NFFT - HOP)) >> 8) : 0;

    float sig = 0.f, env = 0.f;
    #pragma unroll 4
    for (int t = t0; t <= t1; t++) {
        int j = p - (t << 8);
        sig += g_frames[((size_t)(b * TT + t) << 10) + j];
        env += g_win2[j];
    }
    float v = sig / env;
    out[idx] = fminf(fmaxf(v, -1.f), 1.f);
}

// ---------------- launcher -----------------------------------------------------
extern "C" void kernel_launch(void* const* d_in, const int* in_sizes, int n_in,
                              void* d_out, int out_size) {
    (void)in_sizes; (void)n_in; (void)out_size;
    const float* x  = (const float*)d_in[0];
    const float* Wm = (const float*)d_in[1];
    const float* bm = (const float*)d_in[2];
    const float* Wp = (const float*)d_in[3];
    const float* bp = (const float*)d_in[4];
    float* out = (float*)d_out;

    init_tables<<<4, 256>>>();

    dim3 ggrid((2 * NBINS + BN - 1) / BN, MTOT / BM);   // (17, 256)
    gemm_kernel<<<ggrid, 256>>>(x, Wm, bm, Wp, bp);

    cumsum_kernel<<<dim3(5, BATCH), 128>>>();

    frames_kernel<<<MTOT, 256>>>();

    oa_kernel<<<(BATCH * OUTLEN + 255) / 256, 256>>>(out);
}

// round 3
// speedup vs baseline: 1.0366x; 1.0366x over previous
#include <cuda_runtime.h>
#include <math.h>
#include <cstdint>

#define BATCH 16
#define DIMK  1024
#define TT    2048
#define NFFT  1024
#define HOP   256
#define NBINS 513
#define NBP   520
#define MTOT  (BATCH * TT)          // 32768
#define OUTLEN (HOP * (TT - 1))     // 524032

// ---------------- scratch ----------------------------------------------------
__device__ float g_mag[(size_t)MTOT * NBP];
__device__ float g_frq[(size_t)MTOT * NBP];
__device__ float g_frames[(size_t)MTOT * NFFT];
__device__ float g_twr[512];
__device__ float g_twi[512];
__device__ float g_winS[1024];      // hann * (1/1024)  (synthesis)
__device__ float g_win2[1024];      // hann^2           (envelope)

// ---------------- helpers -----------------------------------------------------
__device__ __forceinline__ uint32_t smem_u32(const void* p) {
    uint32_t a;
    asm("{ .reg .u64 t; cvta.to.shared.u64 t, %1; cvt.u32.u64 %0, t; }"
        : "=r"(a) : "l"(p));
    return a;
}
__device__ __forceinline__ void cp16(uint32_t dst, const void* src) {
    asm volatile("cp.async.cg.shared.global [%0], [%1], 16;" :: "r"(dst), "l"(src));
}
#define CP_COMMIT() asm volatile("cp.async.commit_group;")
#define CP_WAIT0()  asm volatile("cp.async.wait_group 0;" ::: "memory")

__device__ __forceinline__ void fma2(unsigned long long& d,
                                     unsigned long long a, unsigned long long b) {
    asm("fma.rn.f32x2 %0, %1, %2, %0;" : "+l"(d) : "l"(a), "l"(b));
}
__device__ __forceinline__ unsigned long long dup2(float v) {
    unsigned long long r;
    asm("mov.b64 %0, {%1, %1};" : "=l"(r) : "f"(v));
    return r;
}
__device__ __forceinline__ void unpack2(unsigned long long v, float& lo, float& hi) {
    asm("mov.b64 {%0, %1}, %2;" : "=f"(lo), "=f"(hi) : "l"(v));
}

// ---------------- table init ---------------------------------------------------
__global__ void init_tables() {
    int i = blockIdx.x * blockDim.x + threadIdx.x;
    const float TWO_PI = 6.283185307179586f;
    if (i < 512) {
        float ang = TWO_PI * (float)i / 1024.0f;
        g_twr[i] = cosf(ang);
        g_twi[i] = sinf(ang);          // inverse FFT: +sin
    }
    if (i < 1024) {
        float w = 0.5f * (1.0f - cosf(TWO_PI * (float)i / 1024.0f));
        g_winS[i] = w * (1.0f / 1024.0f);
        g_win2[i] = w * w;
    }
}

// ---------------- fused dual GEMM (f32x2) ---------------------------------------
// C[m][n]: m = b*2048 + t, n<513 mag head, 513..1025 phase head.
// Tile: TM=256, TN=128, BK=16, 256 threads (16x16), per-thread 16m x 8n.
#define TM 256
#define TN 128
#define BK 16
#define AS_BUF 4096            // BK*TM floats per buffer
#define BS_ROW 192             // 16 groups * 12 floats (8 data + 4 pad)
#define BS_BUF (BK * BS_ROW)   // 3072 floats
#define GEMM_SMEM ((2 * AS_BUF + 2 * BS_BUF) * 4)   // 57344 B

__global__ void __launch_bounds__(256, 1) gemm_f32x2(
    const float* __restrict__ x,
    const float* __restrict__ Wm, const float* __restrict__ bm,
    const float* __restrict__ Wp, const float* __restrict__ bp)
{
    extern __shared__ float sm[];
    float* As = sm;                       // [2][BK][256]
    float* Bs = sm + 2 * AS_BUF;          // [2][BK][192]
    uint32_t as_base = smem_u32(As);

    int tid = threadIdx.x;
    int tx = tid & 15, ty = tid >> 4;
    int n0 = blockIdx.x * TN;
    int m0 = blockIdx.y * TM;
    int b  = m0 >> 11;
    int t0 = m0 & (TT - 1);
    const float* xb = x + (size_t)b * DIMK * TT + t0;

    // B row for this thread's staging lane
    int nl = tid >> 1;                    // 0..127 local n row
    int kq = (tid & 1) * 8;               // k-offset within chunk
    int ng = n0 + nl;
    const float* wrow = nullptr;
    if (ng < NBINS)          wrow = Wm + (size_t)ng * DIMK;
    else if (ng < 2 * NBINS) wrow = Wp + (size_t)(ng - NBINS) * DIMK;
    int bcol = (nl >> 3) * 12 + (nl & 7);

    unsigned long long acc[8][8];
    #pragma unroll
    for (int i = 0; i < 8; i++)
        #pragma unroll
        for (int j = 0; j < 8; j++) acc[i][j] = 0ull;

    float4 br0, br1;

    // ---- staging helpers (inlined) ----
    // A chunk via cp.async: 1024 x 16B, 4 per thread
    #define ISSUE_A(k0_, buf_) do {                                           \
        uint32_t dstb = as_base + (uint32_t)((buf_) * AS_BUF) * 4;            \
        _Pragma("unroll")                                                     \
        for (int i_ = 0; i_ < 4; i_++) {                                      \
            int c_ = tid + i_ * 256;                                          \
            int kk_ = c_ >> 6;                                                \
            int mq_ = (c_ & 63) << 2;                                         \
            cp16(dstb + (uint32_t)(kk_ * 256 + mq_) * 4,                      \
                 xb + (size_t)((k0_) + kk_) * TT + mq_);                      \
        }                                                                     \
    } while (0)

    #define LOAD_B(k0_) do {                                                  \
        if (wrow) {                                                           \
            br0 = *reinterpret_cast<const float4*>(wrow + (k0_) + kq);        \
            br1 = *reinterpret_cast<const float4*>(wrow + (k0_) + kq + 4);    \
        } else {                                                              \
            br0 = make_float4(0.f, 0.f, 0.f, 0.f);                            \
            br1 = br0;                                                        \
        }                                                                     \
    } while (0)

    #define STS_B(buf_) do {                                                  \
        float* d_ = Bs + (buf_) * BS_BUF + bcol;                              \
        d_[(kq + 0) * BS_ROW] = br0.x;  d_[(kq + 1) * BS_ROW] = br0.y;        \
        d_[(kq + 2) * BS_ROW] = br0.z;  d_[(kq + 3) * BS_ROW] = br0.w;        \
        d_[(kq + 4) * BS_ROW] = br1.x;  d_[(kq + 5) * BS_ROW] = br1.y;        \
        d_[(kq + 6) * BS_ROW] = br1.z;  d_[(kq + 7) * BS_ROW] = br1.w;        \
    } while (0)

    // prologue: chunk 0 -> buf 0
    ISSUE_A(0, 0);
    CP_COMMIT();
    LOAD_B(0);
    CP_WAIT0();
    STS_B(0);
    __syncthreads();

    const int NCH = DIMK / BK;   // 64
    #pragma unroll 1
    for (int c = 0; c < NCH; c++) {
        int s = c & 1;
        if (c + 1 < NCH) {
            ISSUE_A((c + 1) * BK, s ^ 1);
            CP_COMMIT();
            LOAD_B((c + 1) * BK);
        }
        // compute on buffer s
        const float* Ab = As + s * AS_BUF + ty * 16;
        const float* Bb = Bs + s * BS_BUF + tx * 12;
        #pragma unroll 2
        for (int kk = 0; kk < BK; kk++) {
            const ulonglong2* ar = reinterpret_cast<const ulonglong2*>(Ab + kk * 256);
            ulonglong2 a01 = ar[0], a23 = ar[1], a45 = ar[2], a67 = ar[3];
            unsigned long long ap[8] = {a01.x, a01.y, a23.x, a23.y,
                                        a45.x, a45.y, a67.x, a67.y};
            float4 b0 = *reinterpret_cast<const float4*>(Bb + kk * BS_ROW);
            float4 b1 = *reinterpret_cast<const float4*>(Bb + kk * BS_ROW + 4);
            unsigned long long bd[8] = {dup2(b0.x), dup2(b0.y), dup2(b0.z), dup2(b0.w),
                                        dup2(b1.x), dup2(b1.y), dup2(b1.z), dup2(b1.w)};
            #pragma unroll
            for (int mp = 0; mp < 8; mp++)
                #pragma unroll
                for (int j = 0; j < 8; j++)
                    fma2(acc[mp][j], ap[mp], bd[j]);
        }
        if (c + 1 < NCH) {
            CP_WAIT0();
            STS_B(s ^ 1);
            __syncthreads();
        }
    }

    // epilogue
    const float PI_F = 3.14159265358979323846f;
    #pragma unroll
    for (int mp = 0; mp < 8; mp++) {
        int mlo = m0 + ty * 16 + mp * 2;
        size_t rlo = (size_t)mlo * NBP;
        size_t rhi = rlo + NBP;
        #pragma unroll
        for (int j = 0; j < 8; j++) {
            int n = n0 + tx * 8 + j;
            float vlo, vhi;
            unpack2(acc[mp][j], vlo, vhi);
            if (n < NBINS) {
                float bb = bm[n];
                float a = fminf(fmaxf(vlo + bb, -10.f), 10.f);
                float c2 = fminf(fmaxf(vhi + bb, -10.f), 10.f);
                g_mag[rlo + n] = expf(a);
                g_mag[rhi + n] = expf(c2);
            } else if (n < 2 * NBINS) {
                int nn = n - NBINS;
                float bb = bp[nn];
                float a = fminf(fmaxf(vlo + bb, -PI_F), PI_F);
                float c2 = fminf(fmaxf(vhi + bb, -PI_F), PI_F);
                g_frq[rlo + nn] = a;
                g_frq[rhi + nn] = c2;
            }
        }
    }
    #undef ISSUE_A
    #undef LOAD_B
    #undef STS_B
}

// ---------------- cumsum along time (in place) -----------------------------------
__global__ void cumsum_kernel() {
    int n = blockIdx.x * 128 + threadIdx.x;
    int b = blockIdx.y;
    if (n >= NBINS) return;
    size_t base = (size_t)b * TT * NBP + n;
    float acc = 0.f;
    #pragma unroll 8
    for (int t = 0; t < TT; t++) {
        size_t off = base + (size_t)t * NBP;
        acc += g_frq[off];
        g_frq[off] = acc;
    }
}

// ---------------- per-frame irfft(1024): radix-2 stage PAIRS ----------------------
__global__ __launch_bounds__(256) void frames_kernel() {
    __shared__ float sre[513];
    __shared__ float sim[513];
    __shared__ float wre[1024];
    __shared__ float wim[1024];
    __shared__ float twr[512];
    __shared__ float twi[512];

    int f = blockIdx.x;
    int tid = threadIdx.x;
    size_t base = (size_t)f * NBP;

    for (int i = tid; i < 512; i += 256) {
        twr[i] = g_twr[i];
        twi[i] = g_twi[i];
    }
    for (int n = tid; n < 513; n += 256) {
        float mg = g_mag[base + n];
        float ph = g_frq[base + n];
        float s, c;
        sincosf(ph, &s, &c);
        sre[n] = mg * c;
        sim[n] = mg * s;
    }
    __syncthreads();

    for (int k = tid; k < 1024; k += 256) {
        int j = __brev((unsigned)k) >> 22;
        if (j <= 512) {
            wre[k] = sre[j];
            wim[k] = sim[j];
        } else {
            int src = 1024 - j;
            wre[k] = sre[src];
            wim[k] = -sim[src];
        }
    }
    __syncthreads();

    size_t ob = (size_t)f * NFFT;

    // 5 fused stage-pairs (stages s=2p+1 and s+1)
    #pragma unroll
    for (int p = 0; p < 5; p++) {
        int s = 2 * p + 1;
        int h = 1 << (2 * p);
        int lowmask = h - 1;
        int bi = ((tid >> (2 * p)) << (2 * p + 2)) | (tid & lowmask);
        int k1 = (tid & lowmask) << (10 - s);
        int k2 = k1 >> 1;

        float x0r = wre[bi],         x0i = wim[bi];
        float x1r = wre[bi + h],     x1i = wim[bi + h];
        float x2r = wre[bi + 2 * h], x2i = wim[bi + 2 * h];
        float x3r = wre[bi + 3 * h], x3i = wim[bi + 3 * h];

        float w1r = twr[k1], w1i = twi[k1];
        // stage s
        float t1r = x1r * w1r - x1i * w1i;
        float t1i = x1r * w1i + x1i * w1r;
        float a0r = x0r + t1r, a0i = x0i + t1i;
        float a1r = x0r - t1r, a1i = x0i - t1i;
        float t2r = x3r * w1r - x3i * w1i;
        float t2i = x3r * w1i + x3i * w1r;
        float a2r = x2r + t2r, a2i = x2i + t2i;
        float a3r = x2r - t2r, a3i = x2i - t2i;

        // stage s+1; twiddle for (a1,a3) pair is W^k2 * i
        float w2r = twr[k2], w2i = twi[k2];
        float u0r = a2r * w2r - a2i * w2i;
        float u0i = a2r * w2i + a2i * w2r;
        float cr  = a3r * w2r - a3i * w2i;
        float ci  = a3r * w2i + a3i * w2r;
        float u1r = -ci, u1i = cr;       // * i

        float y0r = a0r + u0r, y0i = a0i + u0i;
        float y2r = a0r - u0r, y2i = a0i - u0i;
        float y1r = a1r + u1r, y1i = a1i + u1i;
        float y3r = a1r - u1r, y3i = a1i - u1i;

        if (p < 4) {
            __syncthreads();   // guard WAR against other threads' reads
            wre[bi] = y0r;         wim[bi] = y0i;
            wre[bi + h] = y1r;     wim[bi + h] = y1i;
            wre[bi + 2 * h] = y2r; wim[bi + 2 * h] = y2i;
            wre[bi + 3 * h] = y3r; wim[bi + 3 * h] = y3i;
            __syncthreads();
        } else {
            // final: natural order, bi = tid; windowed real output, coalesced
            g_frames[ob + tid]       = y0r * g_winS[tid];
            g_frames[ob + tid + 256] = y1r * g_winS[tid + 256];
            g_frames[ob + tid + 512] = y2r * g_winS[tid + 512];
            g_frames[ob + tid + 768] = y3r * g_winS[tid + 768];
        }
    }
}

// ---------------- overlap-add ------------------------------------------------------
__global__ void oa_kernel(float* __restrict__ out) {
    int idx = blockIdx.x * 256 + threadIdx.x;
    if (idx >= BATCH * OUTLEN) return;
    int b = idx / OUTLEN;
    int s = idx - b * OUTLEN;
    int p = s + NFFT / 2;

    int t1 = p >> 8;  if (t1 > TT - 1) t1 = TT - 1;
    int t0 = (p >= NFFT - HOP) ? ((p - (NFFT - HOP)) >> 8) : 0;

    float sig = 0.f, env = 0.f;
    #pragma unroll 4
    for (int t = t0; t <= t1; t++) {
        int j = p - (t << 8);
        sig += g_frames[((size_t)(b * TT + t) << 10) + j];
        env += g_win2[j];
    }
    float v = sig / env;
    out[idx] = fminf(fmaxf(v, -1.f), 1.f);
}

// ---------------- launcher ----------------------------------------------------------
extern "C" void kernel_launch(void* const* d_in, const int* in_sizes, int n_in,
                              void* d_out, int out_size) {
    (void)in_sizes; (void)n_in; (void)out_size;
    const float* x  = (const float*)d_in[0];
    const float* Wm = (const float*)d_in[1];
    const float* bm = (const float*)d_in[2];
    const float* Wp = (const float*)d_in[3];
    const float* bp = (const float*)d_in[4];
    float* out = (float*)d_out;

    cudaFuncSetAttribute(gemm_f32x2, cudaFuncAttributeMaxDynamicSharedMemorySize,
                         GEMM_SMEM);

    init_tables<<<4, 256>>>();

    dim3 ggrid((2 * NBINS + TN - 1) / TN, MTOT / TM);   // (9, 128)
    gemm_f32x2<<<ggrid, 256, GEMM_SMEM>>>(x, Wm, bm, Wp, bp);

    cumsum_kernel<<<dim3(5, BATCH), 128>>>();
    frames_kernel<<<MTOT, 256>>>();
    oa_kernel<<<(BATCH * OUTLEN + 255) / 256, 256>>>(out);
}

// round 4
// speedup vs baseline: 1.2856x; 1.2402x over previous
#include <cuda_runtime.h>
#include <cuda_bf16.h>
#include <math.h>
#include <cstdint>

#define BATCH 16
#define DIMK  1024
#define TT    2048
#define NFFT  1024
#define HOP   256
#define NBINS 513
#define NBP   520
#define MTOT  (BATCH * TT)          // 32768
#define OUTLEN (HOP * (TT - 1))     // 524032

#define NPAD  1152
#define TLM   128
#define TLN   128
#define KC    32
#define NCHG  (DIMK / KC)           // 32

static constexpr size_t ASZ = (size_t)MTOT * DIMK;
static constexpr size_t BSZ = (size_t)NPAD * DIMK;

// smem geometry for gemm
#define SROW        80
#define SPLIT_BYTES (128 * SROW)        // 10240
#define AB_BYTES    (3 * SPLIT_BYTES)   // 30720
#define STAGE_BYTES (2 * AB_BYTES)      // 61440 (A then B)
#define GEMM_SMEM   (2 * STAGE_BYTES)   // 122880

// ---------------- scratch ----------------------------------------------------
__device__ __nv_bfloat16 g_A[3ull * ASZ];
__device__ __nv_bfloat16 g_B[3ull * BSZ];
__device__ float g_mag[(size_t)MTOT * NBP];
__device__ float g_frq[(size_t)MTOT * NBP];
__device__ float g_frames[(size_t)MTOT * NFFT];
__device__ float g_c1024[512];
__device__ float g_s1024[512];
__device__ float g_c512[256];
__device__ float g_s512[256];
__device__ float g_winS[1024];   // hann / 1024
__device__ float g_win2[1024];   // hann^2

// ---------------- helpers -----------------------------------------------------
__device__ __forceinline__ uint32_t smem_u32(const void* p) {
    uint32_t a;
    asm("{ .reg .u64 t; cvta.to.shared.u64 t, %1; cvt.u32.u64 %0, t; }"
        : "=r"(a) : "l"(p));
    return a;
}
__device__ __forceinline__ void cp16(uint32_t dst, const void* src) {
    asm volatile("cp.async.cg.shared.global [%0], [%1], 16;" :: "r"(dst), "l"(src));
}
#define CP_COMMIT() asm volatile("cp.async.commit_group;")
#define CP_WAIT0()  asm volatile("cp.async.wait_group 0;" ::: "memory")

__device__ __forceinline__ void ldsm_x4(uint32_t& r0, uint32_t& r1,
                                        uint32_t& r2, uint32_t& r3, uint32_t a) {
    asm volatile("ldmatrix.sync.aligned.m8n8.x4.shared.b16 {%0,%1,%2,%3}, [%4];"
                 : "=r"(r0), "=r"(r1), "=r"(r2), "=r"(r3) : "r"(a));
}
__device__ __forceinline__ void mma_bf16(float* c, const uint32_t* a, const uint32_t* b) {
    asm volatile(
        "mma.sync.aligned.m16n8k16.row.col.f32.bf16.bf16.f32 "
        "{%0,%1,%2,%3}, {%4,%5,%6,%7}, {%8,%9}, {%0,%1,%2,%3};"
        : "+f"(c[0]), "+f"(c[1]), "+f"(c[2]), "+f"(c[3])
        : "r"(a[0]), "r"(a[1]), "r"(a[2]), "r"(a[3]), "r"(b[0]), "r"(b[1]));
}

// ---------------- table init ---------------------------------------------------
__global__ void init_tables() {
    int i = blockIdx.x * blockDim.x + threadIdx.x;
    const float TWO_PI = 6.283185307179586f;
    if (i < 512) {
        float a = TWO_PI * (float)i / 1024.0f;
        g_c1024[i] = cosf(a);
        g_s1024[i] = sinf(a);
    }
    if (i < 256) {
        float a = TWO_PI * (float)i / 512.0f;
        g_c512[i] = cosf(a);
        g_s512[i] = sinf(a);
    }
    if (i < 1024) {
        float w = 0.5f * (1.0f - cosf(TWO_PI * (float)i / 1024.0f));
        g_winS[i] = w * (1.0f / 1024.0f);
        g_win2[i] = w * w;
    }
}

// ---------------- split prep ----------------------------------------------------
__device__ __forceinline__ void split3(float v, __nv_bfloat16& h0,
                                       __nv_bfloat16& h1, __nv_bfloat16& h2) {
    h0 = __float2bfloat16(v);
    float r1 = v - __bfloat162float(h0);
    h1 = __float2bfloat16(r1);
    float r2 = r1 - __bfloat162float(h1);
    h2 = __float2bfloat16(r2);
}

// x [B][K][T] -> g_A[split][m=b*T+t][k]
__global__ void split_x_kernel(const float* __restrict__ x) {
    __shared__ float tile[32][33];
    int b = blockIdx.z;
    int k0 = blockIdx.y * 32, t0 = blockIdx.x * 32;
    int tx = threadIdx.x, ty = threadIdx.y;
    const float* src = x + ((size_t)b * DIMK + k0) * TT + t0;
    #pragma unroll
    for (int r = 0; r < 4; r++)
        tile[ty + 8 * r][tx] = src[(size_t)(ty + 8 * r) * TT + tx];
    __syncthreads();
    #pragma unroll
    for (int r = 0; r < 4; r++) {
        float v = tile[tx][ty + 8 * r];
        size_t m = (size_t)b * TT + t0 + ty + 8 * r;
        __nv_bfloat16 h0, h1, h2;
        split3(v, h0, h1, h2);
        size_t o = m * DIMK + k0 + tx;
        g_A[o] = h0;
        g_A[ASZ + o] = h1;
        g_A[2 * ASZ + o] = h2;
    }
}

__global__ void split_w_kernel(const float* __restrict__ Wm,
                               const float* __restrict__ Wp) {
    int n = blockIdx.x;
    const float* src = nullptr;
    if (n < NBINS) src = Wm + (size_t)n * DIMK;
    else if (n < 2 * NBINS) src = Wp + (size_t)(n - NBINS) * DIMK;
    for (int k = threadIdx.x; k < DIMK; k += 256) {
        float v = src ? src[k] : 0.0f;
        __nv_bfloat16 h0, h1, h2;
        split3(v, h0, h1, h2);
        size_t o = (size_t)n * DIMK + k;
        g_B[o] = h0;
        g_B[BSZ + o] = h1;
        g_B[2 * BSZ + o] = h2;
    }
}

// ---------------- HMMA split-bf16 dual GEMM ---------------------------------------
__global__ void __launch_bounds__(256, 1) gemm_hmma(
    const float* __restrict__ bmag, const float* __restrict__ bphs)
{
    extern __shared__ char smraw[];
    uint32_t smem_base = smem_u32(smraw);

    int tid = threadIdx.x;
    int lane = tid & 31, wid = tid >> 5;
    int wm = wid >> 2, wn = wid & 3;
    int n0 = blockIdx.x * TLN;
    int m0 = blockIdx.y * TLM;
    int nprod = (blockIdx.x < 4) ? 3 : 6;
    int nsplit = (blockIdx.x < 4) ? 2 : 3;

    float acc[4][4][4];
    #pragma unroll
    for (int mt = 0; mt < 4; mt++)
        #pragma unroll
        for (int nt = 0; nt < 4; nt++)
            #pragma unroll
            for (int r = 0; r < 4; r++) acc[mt][nt][r] = 0.f;

    // per-thread ldmatrix address pieces
    uint32_t aoff = (uint32_t)((wm * 64 + (lane & 15)) * SROW + (lane >> 4) * 16);
    uint32_t boff = (uint32_t)((wn * 32 + (lane & 7) + (lane >> 4) * 8) * SROW +
                               ((lane >> 3) & 1) * 16);

    #define ISSUE_CHUNK(k0_, buf_) do {                                          \
        uint32_t stage_ = smem_base + (uint32_t)(buf_) * STAGE_BYTES;             \
        _Pragma("unroll")                                                         \
        for (int i_ = 0; i_ < 12; i_++) {                                         \
            int v_ = tid + i_ * 256;                                              \
            int isB_ = v_ >= 1536;                                                \
            int r_ = isB_ ? v_ - 1536 : v_;                                       \
            int p_ = r_ >> 9;                                                     \
            int rem_ = r_ & 511;                                                  \
            int row_ = rem_ >> 2;                                                 \
            int ch_ = rem_ & 3;                                                   \
            if (p_ < nsplit) {                                                    \
                const __nv_bfloat16* s_ = isB_                                    \
                    ? g_B + (size_t)p_ * BSZ + (size_t)(n0 + row_) * DIMK + (k0_) + ch_ * 8 \
                    : g_A + (size_t)p_ * ASZ + (size_t)(m0 + row_) * DIMK + (k0_) + ch_ * 8; \
                uint32_t d_ = stage_ + (isB_ ? AB_BYTES : 0) +                    \
                              (uint32_t)(p_ * SPLIT_BYTES + row_ * SROW + ch_ * 16); \
                cp16(d_, s_);                                                     \
            }                                                                     \
        }                                                                         \
        CP_COMMIT();                                                              \
    } while (0)

    ISSUE_CHUNK(0, 0);
    CP_WAIT0();
    __syncthreads();

    #pragma unroll 1
    for (int c = 0; c < NCHG; c++) {
        int s = c & 1;
        if (c + 1 < NCHG) ISSUE_CHUNK((c + 1) * KC, s ^ 1);

        uint32_t sA = smem_base + (uint32_t)s * STAGE_BYTES;
        uint32_t sB = sA + AB_BYTES;

        #pragma unroll
        for (int ks = 0; ks < 2; ks++) {
            uint32_t afr[3][4][4];
            uint32_t bfr[3][4][2];
            #pragma unroll
            for (int p = 0; p < 3; p++) {
                if (p < nsplit) {
                    #pragma unroll
                    for (int mt = 0; mt < 4; mt++) {
                        uint32_t ad = sA + (uint32_t)p * SPLIT_BYTES + aoff +
                                      (uint32_t)(mt * 16 * SROW + ks * 32);
                        ldsm_x4(afr[p][mt][0], afr[p][mt][1],
                                afr[p][mt][2], afr[p][mt][3], ad);
                    }
                    uint32_t bd = sB + (uint32_t)p * SPLIT_BYTES + boff + (uint32_t)(ks * 32);
                    ldsm_x4(bfr[p][0][0], bfr[p][0][1], bfr[p][1][0], bfr[p][1][1], bd);
                    ldsm_x4(bfr[p][2][0], bfr[p][2][1], bfr[p][3][0], bfr[p][3][1],
                            bd + 16 * SROW);
                }
            }
            #define PROD(pa_, pb_)                                                \
                _Pragma("unroll")                                                 \
                for (int mt = 0; mt < 4; mt++)                                    \
                    _Pragma("unroll")                                             \
                    for (int nt = 0; nt < 4; nt++)                                \
                        mma_bf16(acc[mt][nt], afr[pa_][mt], bfr[pb_][nt]);
            if (nprod == 3) {
                PROD(0, 0); PROD(0, 1); PROD(1, 0);
            } else {
                PROD(0, 0); PROD(0, 1); PROD(1, 0);
                PROD(0, 2); PROD(2, 0); PROD(1, 1);
            }
            #undef PROD
        }

        if (c + 1 < NCHG) {
            CP_WAIT0();
            __syncthreads();
        }
    }
    #undef ISSUE_CHUNK

    // epilogue
    const float PI_F = 3.14159265358979323846f;
    #pragma unroll
    for (int mt = 0; mt < 4; mt++) {
        #pragma unroll
        for (int nt = 0; nt < 4; nt++) {
            int r0 = m0 + wm * 64 + mt * 16 + (lane >> 2);
            int cg = n0 + wn * 32 + nt * 8 + (lane & 3) * 2;
            #pragma unroll
            for (int hh = 0; hh < 2; hh++) {
                int m = r0 + hh * 8;
                size_t row = (size_t)m * NBP;
                #pragma unroll
                for (int e = 0; e < 2; e++) {
                    int ng = cg + e;
                    float v = acc[mt][nt][hh * 2 + e];
                    if (ng < NBINS) {
                        v += __ldg(bmag + ng);
                        v = fminf(fmaxf(v, -10.f), 10.f);
                        g_mag[row + ng] = expf(v);
                    } else if (ng < 2 * NBINS) {
                        int nn = ng - NBINS;
                        v += __ldg(bphs + nn);
                        v = fminf(fmaxf(v, -PI_F), PI_F);
                        g_frq[row + nn] = v;
                    }
                }
            }
        }
    }
}

// ---------------- cumsum along time (in place) -------------------------------------
__global__ void cumsum_kernel() {
    int n = blockIdx.x * 128 + threadIdx.x;
    int b = blockIdx.y;
    if (n >= NBINS) return;
    size_t base = (size_t)b * TT * NBP + n;
    float acc = 0.f;
    #pragma unroll 8
    for (int t = 0; t < TT; t++) {
        size_t off = base + (size_t)t * NBP;
        acc += g_frq[off];
        g_frq[off] = acc;
    }
}

// ---------------- frames: real irfft(1024) via 512-pt complex IFFT ------------------
__global__ __launch_bounds__(128) void frames_kernel() {
    __shared__ float sxr[513];
    __shared__ float sxi[513];
    __shared__ float wre[512];
    __shared__ float wim[512];
    __shared__ float twr[256];
    __shared__ float twi[256];

    int f = blockIdx.x;
    int tid = threadIdx.x;
    size_t base = (size_t)f * NBP;

    for (int i = tid; i < 256; i += 128) {
        twr[i] = g_c512[i];
        twi[i] = g_s512[i];
    }
    for (int n = tid; n < 513; n += 128) {
        float mg = g_mag[base + n];
        float ph = g_frq[base + n];
        float s, c;
        sincosf(ph, &s, &c);
        float im = mg * s;
        if (n == 0 || n == 512) im = 0.f;   // real DC/Nyquist (irfft semantics)
        sxr[n] = mg * c;
        sxi[n] = im;
    }
    __syncthreads();

    // build G in bit-reversed order:
    // G[j] = (X[j]+conj(X[512-j])) + i * e^{2pi i j/1024} * (X[j]-conj(X[512-j]))
    #pragma unroll
    for (int q = 0; q < 4; q++) {
        int k = tid + q * 128;
        int j = __brev((unsigned)k) >> 23;
        float x0r = sxr[j],       x0i = sxi[j];
        float x1r = sxr[512 - j], x1i = sxi[512 - j];
        float ar = x0r + x1r, ai = x0i - x1i;
        float br = x0r - x1r, bi = x0i + x1i;
        float tr = g_c1024[j], ti = g_s1024[j];
        wre[k] = ar - (tr * bi + ti * br);
        wim[k] = ai + (tr * br - ti * bi);
    }
    __syncthreads();

    // 4 fused radix-2 stage pairs (stages 1..8 of 512-pt inverse DIT)
    #pragma unroll
    for (int p = 0; p < 4; p++) {
        int h = 1 << (2 * p);
        int lm = h - 1;
        int bi_ = ((tid >> (2 * p)) << (2 * p + 2)) | (tid & lm);
        int k1 = (tid & lm) << (8 - 2 * p);
        int k2 = k1 >> 1;

        float x0r = wre[bi_],         x0i = wim[bi_];
        float x1r = wre[bi_ + h],     x1i = wim[bi_ + h];
        float x2r = wre[bi_ + 2 * h], x2i = wim[bi_ + 2 * h];
        float x3r = wre[bi_ + 3 * h], x3i = wim[bi_ + 3 * h];

        float w1r = twr[k1], w1i = twi[k1];
        float t1r = x1r * w1r - x1i * w1i;
        float t1i = x1r * w1i + x1i * w1r;
        float a0r = x0r + t1r, a0i = x0i + t1i;
        float a1r = x0r - t1r, a1i = x0i - t1i;
        float t2r = x3r * w1r - x3i * w1i;
        float t2i = x3r * w1i + x3i * w1r;
        float a2r = x2r + t2r, a2i = x2i + t2i;
        float a3r = x2r - t2r, a3i = x2i - t2i;

        float w2r = twr[k2], w2i = twi[k2];
        float u0r = a2r * w2r - a2i * w2i;
        float u0i = a2r * w2i + a2i * w2r;
        float cr  = a3r * w2r - a3i * w2i;
        float ci  = a3r * w2i + a3i * w2r;
        float u1r = -ci, u1i = cr;           // * (+i): inverse FFT

        __syncthreads();
        wre[bi_] = a0r + u0r;         wim[bi_] = a0i + u0i;
        wre[bi_ + h] = a1r + u1r;     wim[bi_ + h] = a1i + u1i;
        wre[bi_ + 2 * h] = a0r - u0r; wim[bi_ + 2 * h] = a0i - u0i;
        wre[bi_ + 3 * h] = a1r - u1r; wim[bi_ + 3 * h] = a1i - u1i;
        __syncthreads();
    }

    // final stage (9) + interleaved windowed output (1/1024 folded in g_winS)
    size_t ob = (size_t)f * NFFT;
    #pragma unroll
    for (int uu = 0; uu < 2; uu++) {
        int u = tid + uu * 128;
        float wr = twr[u], wi = twi[u];
        float ar = wre[u],       ai = wim[u];
        float br = wre[u + 256], bi = wim[u + 256];
        float tr = br * wr - bi * wi;
        float ti = br * wi + bi * wr;
        float y0r = ar + tr, y0i = ai + ti;
        float y1r = ar - tr, y1i = ai - ti;
        float2 o0 = make_float2(y0r * g_winS[2 * u], y0i * g_winS[2 * u + 1]);
        float2 o1 = make_float2(y1r * g_winS[2 * u + 512], y1i * g_winS[2 * u + 513]);
        *reinterpret_cast<float2*>(&g_frames[ob + 2 * u]) = o0;
        *reinterpret_cast<float2*>(&g_frames[ob + 2 * u + 512]) = o1;
    }
}

// ---------------- overlap-add ---------------------------------------------------------
__global__ void oa_kernel(float* __restrict__ out) {
    int idx = blockIdx.x * 256 + threadIdx.x;
    if (idx >= BATCH * OUTLEN) return;
    int b = idx / OUTLEN;
    int s = idx - b * OUTLEN;
    int p = s + NFFT / 2;

    int t1 = p >> 8;  if (t1 > TT - 1) t1 = TT - 1;
    int t0 = (p >= NFFT - HOP) ? ((p - (NFFT - HOP)) >> 8) : 0;

    float sig = 0.f, env = 0.f;
    #pragma unroll 4
    for (int t = t0; t <= t1; t++) {
        int j = p - (t << 8);
        sig += g_frames[((size_t)(b * TT + t) << 10) + j];
        env += g_win2[j];
    }
    float v = sig / env;
    out[idx] = fminf(fmaxf(v, -1.f), 1.f);
}

// ---------------- launcher --------------------------------------------------------------
extern "C" void kernel_launch(void* const* d_in, const int* in_sizes, int n_in,
                              void* d_out, int out_size) {
    (void)in_sizes; (void)n_in; (void)out_size;
    const float* x  = (const float*)d_in[0];
    const float* Wm = (const float*)d_in[1];
    const float* bm = (const float*)d_in[2];
    const float* Wp = (const float*)d_in[3];
    const float* bp = (const float*)d_in[4];
    float* out = (float*)d_out;

    cudaFuncSetAttribute(gemm_hmma, cudaFuncAttributeMaxDynamicSharedMemorySize,
                         GEMM_SMEM);

    init_tables<<<4, 256>>>();
    split_x_kernel<<<dim3(TT / 32, DIMK / 32, BATCH), dim3(32, 8)>>>(x);
    split_w_kernel<<<NPAD, 256>>>(Wm, Wp);

    gemm_hmma<<<dim3(NPAD / TLN, MTOT / TLM), 256, GEMM_SMEM>>>(bm, bp);

    cumsum_kernel<<<dim3(5, BATCH), 128>>>();
    frames_kernel<<<MTOT, 128>>>();
    oa_kernel<<<(BATCH * OUTLEN + 255) / 256, 256>>>(out);
}

// round 5
// speedup vs baseline: 1.6119x; 1.2539x over previous
#include <cuda_runtime.h>
#include <cuda_bf16.h>
#include <math.h>
#include <cstdint>

#define BATCH 16
#define DIMK  1024
#define TT    2048
#define NFFT  1024
#define HOP   256
#define NBINS 513
#define NBP   520
#define MTOT  (BATCH * TT)          // 32768
#define OUTLEN (HOP * (TT - 1))     // 524032

#define NPAD  1024                  // 8 full n-tiles; bins 511/512 (phase) via SIMT
#define TLM   128
#define TLN   128
#define KC    32
#define NCHG  (DIMK / KC)           // 32
#define NSPLIT 2

static constexpr size_t ASZ = (size_t)MTOT * DIMK;
static constexpr size_t BSZ = (size_t)NPAD * DIMK;

// smem geometry: per split 128 rows x 80B (64B data + 16 pad)
#define SROW        80
#define SPLIT_BYTES (128 * SROW)              // 10240
#define AB_BYTES    (NSPLIT * SPLIT_BYTES)    // 20480
#define STAGE_BYTES (2 * AB_BYTES)            // 40960 (A then B)
#define NSTAGE      3
#define GEMM_SMEM   (NSTAGE * STAGE_BYTES)    // 122880

// ---------------- scratch ----------------------------------------------------
__device__ __nv_bfloat16 g_A[(size_t)NSPLIT * ASZ];
__device__ __nv_bfloat16 g_B[(size_t)NSPLIT * BSZ];
__device__ float g_mag[(size_t)MTOT * NBP];
__device__ float g_frq[(size_t)MTOT * NBP];
__device__ float g_frames[(size_t)MTOT * NFFT];
__device__ float g_c1024[512];
__device__ float g_s1024[512];
__device__ float g_c512[256];
__device__ float g_s512[256];
__device__ float g_winS[1024];   // hann / 1024
__device__ float g_win2[1024];   // hann^2

// ---------------- helpers -----------------------------------------------------
__device__ __forceinline__ uint32_t smem_u32(const void* p) {
    uint32_t a;
    asm("{ .reg .u64 t; cvta.to.shared.u64 t, %1; cvt.u32.u64 %0, t; }"
        : "=r"(a) : "l"(p));
    return a;
}
__device__ __forceinline__ void cp16(uint32_t dst, const void* src) {
    asm volatile("cp.async.cg.shared.global [%0], [%1], 16;" :: "r"(dst), "l"(src));
}
#define CP_COMMIT() asm volatile("cp.async.commit_group;")
#define CP_WAIT1()  asm volatile("cp.async.wait_group 1;" ::: "memory")

__device__ __forceinline__ void ldsm_x4(uint32_t& r0, uint32_t& r1,
                                        uint32_t& r2, uint32_t& r3, uint32_t a) {
    asm volatile("ldmatrix.sync.aligned.m8n8.x4.shared.b16 {%0,%1,%2,%3}, [%4];"
                 : "=r"(r0), "=r"(r1), "=r"(r2), "=r"(r3) : "r"(a));
}
__device__ __forceinline__ void mma_bf16(float* c, const uint32_t* a, const uint32_t* b) {
    asm volatile(
        "mma.sync.aligned.m16n8k16.row.col.f32.bf16.bf16.f32 "
        "{%0,%1,%2,%3}, {%4,%5,%6,%7}, {%8,%9}, {%0,%1,%2,%3};"
        : "+f"(c[0]), "+f"(c[1]), "+f"(c[2]), "+f"(c[3])
        : "r"(a[0]), "r"(a[1]), "r"(a[2]), "r"(a[3]), "r"(b[0]), "r"(b[1]));
}

// ---------------- table init ---------------------------------------------------
__global__ void init_tables() {
    int i = blockIdx.x * blockDim.x + threadIdx.x;
    const float TWO_PI = 6.283185307179586f;
    if (i < 512) {
        float a = TWO_PI * (float)i / 1024.0f;
        g_c1024[i] = cosf(a);
        g_s1024[i] = sinf(a);
    }
    if (i < 256) {
        float a = TWO_PI * (float)i / 512.0f;
        g_c512[i] = cosf(a);
        g_s512[i] = sinf(a);
    }
    if (i < 1024) {
        float w = 0.5f * (1.0f - cosf(TWO_PI * (float)i / 1024.0f));
        g_winS[i] = w * (1.0f / 1024.0f);
        g_win2[i] = w * w;
    }
}

// ---------------- split prep (2 terms) --------------------------------------------
__device__ __forceinline__ void split2(float v, __nv_bfloat16& h0, __nv_bfloat16& h1) {
    h0 = __float2bfloat16(v);
    h1 = __float2bfloat16(v - __bfloat162float(h0));
}

// x [B][K][T] -> g_A[split][m=b*T+t][k]
__global__ void split_x_kernel(const float* __restrict__ x) {
    __shared__ float tile[32][33];
    int b = blockIdx.z;
    int k0 = blockIdx.y * 32, t0 = blockIdx.x * 32;
    int tx = threadIdx.x, ty = threadIdx.y;
    const float* src = x + ((size_t)b * DIMK + k0) * TT + t0;
    #pragma unroll
    for (int r = 0; r < 4; r++)
        tile[ty + 8 * r][tx] = src[(size_t)(ty + 8 * r) * TT + tx];
    __syncthreads();
    #pragma unroll
    for (int r = 0; r < 4; r++) {
        float v = tile[tx][ty + 8 * r];
        size_t m = (size_t)b * TT + t0 + ty + 8 * r;
        __nv_bfloat16 h0, h1;
        split2(v, h0, h1);
        size_t o = m * DIMK + k0 + tx;
        g_A[o] = h0;
        g_A[ASZ + o] = h1;
    }
}

// virtual B rows 0..1023: n<513 mag, 513..1023 -> phase bins 0..510
__global__ void split_w_kernel(const float* __restrict__ Wm,
                               const float* __restrict__ Wp) {
    int n = blockIdx.x;
    const float* src = (n < NBINS) ? Wm + (size_t)n * DIMK
                                   : Wp + (size_t)(n - NBINS) * DIMK;
    for (int k = threadIdx.x; k < DIMK; k += 256) {
        float v = src[k];
        __nv_bfloat16 h0, h1;
        split2(v, h0, h1);
        size_t o = (size_t)n * DIMK + k;
        g_B[o] = h0;
        g_B[BSZ + o] = h1;
    }
}

// ---------------- HMMA 2-split dual GEMM (3-stage pipeline) -------------------------
__global__ void __launch_bounds__(256, 1) gemm_hmma(
    const float* __restrict__ bmag, const float* __restrict__ bphs)
{
    extern __shared__ char smraw[];
    uint32_t smem_base = smem_u32(smraw);

    int tid = threadIdx.x;
    int lane = tid & 31, wid = tid >> 5;
    int wm = wid >> 2, wn = wid & 3;
    int n0 = blockIdx.x * TLN;
    int m0 = blockIdx.y * TLM;

    float acc[4][4][4];
    #pragma unroll
    for (int mt = 0; mt < 4; mt++)
        #pragma unroll
        for (int nt = 0; nt < 4; nt++)
            #pragma unroll
            for (int r = 0; r < 4; r++) acc[mt][nt][r] = 0.f;

    uint32_t aoff = (uint32_t)((wm * 64 + (lane & 15)) * SROW + (lane >> 4) * 16);
    uint32_t boff = (uint32_t)((wn * 32 + (lane & 7) + (lane >> 4) * 8) * SROW +
                               ((lane >> 3) & 1) * 16);

    // 2048 cp16 per chunk -> 8 per thread
    #define ISSUE_CHUNK(k0_, buf_) do {                                              \
        uint32_t stage_ = smem_base + (uint32_t)(buf_) * STAGE_BYTES;                 \
        _Pragma("unroll")                                                             \
        for (int i_ = 0; i_ < 8; i_++) {                                              \
            int v_ = tid + i_ * 256;                                                  \
            int isB_ = v_ >= 1024;                                                    \
            int r_ = v_ & 1023;                                                       \
            int p_ = r_ >> 9;                                                         \
            int rem_ = r_ & 511;                                                      \
            int row_ = rem_ >> 2;                                                     \
            int ch_ = rem_ & 3;                                                       \
            const __nv_bfloat16* s_ = isB_                                            \
                ? g_B + (size_t)p_ * BSZ + (size_t)(n0 + row_) * DIMK + (k0_) + ch_ * 8 \
                : g_A + (size_t)p_ * ASZ + (size_t)(m0 + row_) * DIMK + (k0_) + ch_ * 8; \
            uint32_t d_ = stage_ + (isB_ ? AB_BYTES : 0) +                            \
                          (uint32_t)(p_ * SPLIT_BYTES + row_ * SROW + ch_ * 16);      \
            cp16(d_, s_);                                                             \
        }                                                                             \
        CP_COMMIT();                                                                  \
    } while (0)

    ISSUE_CHUNK(0, 0);
    ISSUE_CHUNK(KC, 1);

    #pragma unroll 1
    for (int c = 0; c < NCHG; c++) {
        int s = c % NSTAGE;
        CP_WAIT1();
        __syncthreads();
        if (c + 2 < NCHG) ISSUE_CHUNK((c + 2) * KC, (c + 2) % NSTAGE);

        uint32_t sA = smem_base + (uint32_t)s * STAGE_BYTES;
        uint32_t sB = sA + AB_BYTES;

        #pragma unroll
        for (int ks = 0; ks < 2; ks++) {
            uint32_t afr[NSPLIT][4][4];
            uint32_t bfr[NSPLIT][4][2];
            #pragma unroll
            for (int p = 0; p < NSPLIT; p++) {
                #pragma unroll
                for (int mt = 0; mt < 4; mt++) {
                    uint32_t ad = sA + (uint32_t)p * SPLIT_BYTES + aoff +
                                  (uint32_t)(mt * 16 * SROW + ks * 32);
                    ldsm_x4(afr[p][mt][0], afr[p][mt][1],
                            afr[p][mt][2], afr[p][mt][3], ad);
                }
                uint32_t bd = sB + (uint32_t)p * SPLIT_BYTES + boff + (uint32_t)(ks * 32);
                ldsm_x4(bfr[p][0][0], bfr[p][0][1], bfr[p][1][0], bfr[p][1][1], bd);
                ldsm_x4(bfr[p][2][0], bfr[p][2][1], bfr[p][3][0], bfr[p][3][1],
                        bd + 16 * SROW);
            }
            #define PROD(pa_, pb_)                                                \
                _Pragma("unroll")                                                 \
                for (int mt = 0; mt < 4; mt++)                                    \
                    _Pragma("unroll")                                             \
                    for (int nt = 0; nt < 4; nt++)                                \
                        mma_bf16(acc[mt][nt], afr[pa_][mt], bfr[pb_][nt]);
            PROD(0, 0); PROD(0, 1); PROD(1, 0);
            #undef PROD
        }
    }
    #undef ISSUE_CHUNK

    // epilogue
    const float PI_F = 3.14159265358979323846f;
    #pragma unroll
    for (int mt = 0; mt < 4; mt++) {
        #pragma unroll
        for (int nt = 0; nt < 4; nt++) {
            int r0 = m0 + wm * 64 + mt * 16 + (lane >> 2);
            int cg = n0 + wn * 32 + nt * 8 + (lane & 3) * 2;
            #pragma unroll
            for (int hh = 0; hh < 2; hh++) {
                int m = r0 + hh * 8;
                size_t row = (size_t)m * NBP;
                #pragma unroll
                for (int e = 0; e < 2; e++) {
                    int ng = cg + e;
                    float v = acc[mt][nt][hh * 2 + e];
                    if (ng < NBINS) {
                        v += __ldg(bmag + ng);
                        v = fminf(fmaxf(v, -10.f), 10.f);
                        g_mag[row + ng] = expf(v);
                    } else {
                        int nn = ng - NBINS;     // phase bins 0..510
                        v += __ldg(bphs + nn);
                        v = fminf(fmaxf(v, -PI_F), PI_F);
                        g_frq[row + nn] = v;
                    }
                }
            }
        }
    }
}

// ---------------- phase bins 511, 512: fp32 SIMT dot ---------------------------------
__global__ __launch_bounds__(256) void extra_bins_kernel(
    const float* __restrict__ x, const float* __restrict__ Wp,
    const float* __restrict__ bp)
{
    __shared__ float w0[1024];
    __shared__ float w1[1024];
    int tid = threadIdx.x;
    for (int k = tid; k < 1024; k += 256) {
        w0[k] = Wp[(size_t)511 * DIMK + k];
        w1[k] = Wp[(size_t)512 * DIMK + k];
    }
    __syncthreads();

    int t = blockIdx.x * 256 + tid;
    int b = blockIdx.y;
    const float* xb = x + (size_t)b * DIMK * TT + t;
    float a0 = 0.f, a1 = 0.f;
    #pragma unroll 8
    for (int k = 0; k < DIMK; k++) {
        float xv = xb[(size_t)k * TT];
        a0 = fmaf(xv, w0[k], a0);
        a1 = fmaf(xv, w1[k], a1);
    }
    const float PI_F = 3.14159265358979323846f;
    size_t row = (size_t)(b * TT + t) * NBP;
    g_frq[row + 511] = fminf(fmaxf(a0 + bp[511], -PI_F), PI_F);
    g_frq[row + 512] = fminf(fmaxf(a1 + bp[512], -PI_F), PI_F);
}

// ---------------- cumsum along time (in place) ----------------------------------------
__global__ void cumsum_kernel() {
    int n = blockIdx.x * 128 + threadIdx.x;
    int b = blockIdx.y;
    if (n >= NBINS) return;
    size_t base = (size_t)b * TT * NBP + n;
    float acc = 0.f;
    #pragma unroll 8
    for (int t = 0; t < TT; t++) {
        size_t off = base + (size_t)t * NBP;
        acc += g_frq[off];
        g_frq[off] = acc;
    }
}

// ---------------- frames: real irfft(1024) via 512-pt complex IFFT ---------------------
__global__ __launch_bounds__(128) void frames_kernel() {
    __shared__ float sxr[513];
    __shared__ float sxi[513];
    __shared__ float wre[512];
    __shared__ float wim[512];
    __shared__ float twr[256];
    __shared__ float twi[256];

    int f = blockIdx.x;
    int tid = threadIdx.x;
    size_t base = (size_t)f * NBP;

    for (int i = tid; i < 256; i += 128) {
        twr[i] = g_c512[i];
        twi[i] = g_s512[i];
    }
    for (int n = tid; n < 513; n += 128) {
        float mg = g_mag[base + n];
        float ph = g_frq[base + n];
        float s, c;
        sincosf(ph, &s, &c);
        float im = mg * s;
        if (n == 0 || n == 512) im = 0.f;
        sxr[n] = mg * c;
        sxi[n] = im;
    }
    __syncthreads();

    #pragma unroll
    for (int q = 0; q < 4; q++) {
        int k = tid + q * 128;
        int j = __brev((unsigned)k) >> 23;
        float x0r = sxr[j],       x0i = sxi[j];
        float x1r = sxr[512 - j], x1i = sxi[512 - j];
        float ar = x0r + x1r, ai = x0i - x1i;
        float br = x0r - x1r, bi = x0i + x1i;
        float tr = g_c1024[j], ti = g_s1024[j];
        wre[k] = ar - (tr * bi + ti * br);
        wim[k] = ai + (tr * br - ti * bi);
    }
    __syncthreads();

    #pragma unroll
    for (int p = 0; p < 4; p++) {
        int h = 1 << (2 * p);
        int lm = h - 1;
        int bi_ = ((tid >> (2 * p)) << (2 * p + 2)) | (tid & lm);
        int k1 = (tid & lm) << (8 - 2 * p);
        int k2 = k1 >> 1;

        float x0r = wre[bi_],         x0i = wim[bi_];
        float x1r = wre[bi_ + h],     x1i = wim[bi_ + h];
        float x2r = wre[bi_ + 2 * h], x2i = wim[bi_ + 2 * h];
        float x3r = wre[bi_ + 3 * h], x3i = wim[bi_ + 3 * h];

        float w1r = twr[k1], w1i = twi[k1];
        float t1r = x1r * w1r - x1i * w1i;
        float t1i = x1r * w1i + x1i * w1r;
        float a0r = x0r + t1r, a0i = x0i + t1i;
        float a1r = x0r - t1r, a1i = x0i - t1i;
        float t2r = x3r * w1r - x3i * w1i;
        float t2i = x3r * w1i + x3i * w1r;
        float a2r = x2r + t2r, a2i = x2i + t2i;
        float a3r = x2r - t2r, a3i = x2i - t2i;

        float w2r = twr[k2], w2i = twi[k2];
        float u0r = a2r * w2r - a2i * w2i;
        float u0i = a2r * w2i + a2i * w2r;
        float cr  = a3r * w2r - a3i * w2i;
        float ci  = a3r * w2i + a3i * w2r;
        float u1r = -ci, u1i = cr;

        __syncthreads();
        wre[bi_] = a0r + u0r;         wim[bi_] = a0i + u0i;
        wre[bi_ + h] = a1r + u1r;     wim[bi_ + h] = a1i + u1i;
        wre[bi_ + 2 * h] = a0r - u0r; wim[bi_ + 2 * h] = a0i - u0i;
        wre[bi_ + 3 * h] = a1r - u1r; wim[bi_ + 3 * h] = a1i - u1i;
        __syncthreads();
    }

    size_t ob = (size_t)f * NFFT;
    #pragma unroll
    for (int uu = 0; uu < 2; uu++) {
        int u = tid + uu * 128;
        float wr = twr[u], wi = twi[u];
        float ar = wre[u],       ai = wim[u];
        float br = wre[u + 256], bi = wim[u + 256];
        float tr = br * wr - bi * wi;
        float ti = br * wi + bi * wr;
        float y0r = ar + tr, y0i = ai + ti;
        float y1r = ar - tr, y1i = ai - ti;
        float2 o0 = make_float2(y0r * g_winS[2 * u], y0i * g_winS[2 * u + 1]);
        float2 o1 = make_float2(y1r * g_winS[2 * u + 512], y1i * g_winS[2 * u + 513]);
        *reinterpret_cast<float2*>(&g_frames[ob + 2 * u]) = o0;
        *reinterpret_cast<float2*>(&g_frames[ob + 2 * u + 512]) = o1;
    }
}

// ---------------- overlap-add -----------------------------------------------------------
__global__ void oa_kernel(float* __restrict__ out) {
    int idx = blockIdx.x * 256 + threadIdx.x;
    if (idx >= BATCH * OUTLEN) return;
    int b = idx / OUTLEN;
    int s = idx - b * OUTLEN;
    int p = s + NFFT / 2;

    int t1 = p >> 8;  if (t1 > TT - 1) t1 = TT - 1;
    int t0 = (p >= NFFT - HOP) ? ((p - (NFFT - HOP)) >> 8) : 0;

    float sig = 0.f, env = 0.f;
    #pragma unroll 4
    for (int t = t0; t <= t1; t++) {
        int j = p - (t << 8);
        sig += g_frames[((size_t)(b * TT + t) << 10) + j];
        env += g_win2[j];
    }
    float v = sig / env;
    out[idx] = fminf(fmaxf(v, -1.f), 1.f);
}

// ---------------- launcher ----------------------------------------------------------------
extern "C" void kernel_launch(void* const* d_in, const int* in_sizes, int n_in,
                              void* d_out, int out_size) {
    (void)in_sizes; (void)n_in; (void)out_size;
    const float* x  = (const float*)d_in[0];
    const float* Wm = (const float*)d_in[1];
    const float* bm = (const float*)d_in[2];
    const float* Wp = (const float*)d_in[3];
    const float* bp = (const float*)d_in[4];
    float* out = (float*)d_out;

    cudaFuncSetAttribute(gemm_hmma, cudaFuncAttributeMaxDynamicSharedMemorySize,
                         GEMM_SMEM);

    init_tables<<<4, 256>>>();
    split_x_kernel<<<dim3(TT / 32, DIMK / 32, BATCH), dim3(32, 8)>>>(x);
    split_w_kernel<<<NPAD, 256>>>(Wm, Wp);

    gemm_hmma<<<dim3(NPAD / TLN, MTOT / TLM), 256, GEMM_SMEM>>>(bm, bp);
    extra_bins_kernel<<<dim3(TT / 256, BATCH), 256>>>(x, Wp, bp);

    cumsum_kernel<<<dim3(5, BATCH), 128>>>();
    frames_kernel<<<MTOT, 128>>>();
    oa_kernel<<<(BATCH * OUTLEN + 255) / 256, 256>>>(out);
}

// round 6
// speedup vs baseline: 1.7619x; 1.0930x over previous
#include <cuda_runtime.h>
#include <cuda_bf16.h>
#include <math.h>
#include <cstdint>

#define BATCH 16
#define DIMK  1024
#define TT    2048
#define NFFT  1024
#define HOP   256
#define NBINS 513
#define NBP   520
#define MTOT  (BATCH * TT)          // 32768
#define OUTLEN (HOP * (TT - 1))     // 524032

#define NPAD  1024                  // 8 n-tiles; bins 511/512 (phase) via SIMT
#define TLM   256
#define TLN   128
#define KC    32
#define NCHG  (DIMK / KC)           // 32
#define NSPLIT 2
#define NTHR  512

static constexpr size_t ASZ = (size_t)MTOT * DIMK;
static constexpr size_t BSZ = (size_t)NPAD * DIMK;

// smem: rows of 64B data + 16B pad
#define SROW        80
#define A_SPLIT     (256 * SROW)              // 20480
#define B_SPLIT     (128 * SROW)              // 10240
#define B_BASE      (2 * A_SPLIT)             // 40960
#define STAGE_BYTES (2 * A_SPLIT + 2 * B_SPLIT)  // 61440
#define NSTAGE      3
#define GEMM_SMEM   (NSTAGE * STAGE_BYTES)    // 184320

// ---------------- scratch ----------------------------------------------------
__device__ __nv_bfloat16 g_A[(size_t)NSPLIT * ASZ];
__device__ __nv_bfloat16 g_B[(size_t)NSPLIT * BSZ];
__device__ float g_mag[(size_t)MTOT * NBP];
__device__ float g_frq[(size_t)MTOT * NBP];
__device__ float g_frames[(size_t)MTOT * NFFT];
__device__ float g_c1024[512];
__device__ float g_s1024[512];
__device__ float g_c512[256];
__device__ float g_s512[256];
__device__ float g_winS[1024];
__device__ float g_win2[1024];

// ---------------- helpers -----------------------------------------------------
__device__ __forceinline__ uint32_t smem_u32(const void* p) {
    uint32_t a;
    asm("{ .reg .u64 t; cvta.to.shared.u64 t, %1; cvt.u32.u64 %0, t; }"
        : "=r"(a) : "l"(p));
    return a;
}
__device__ __forceinline__ void cp16(uint32_t dst, const void* src) {
    asm volatile("cp.async.cg.shared.global [%0], [%1], 16;" :: "r"(dst), "l"(src));
}
#define CP_COMMIT() asm volatile("cp.async.commit_group;")
#define CP_WAIT1()  asm volatile("cp.async.wait_group 1;" ::: "memory")

__device__ __forceinline__ void ldsm_x4(uint32_t& r0, uint32_t& r1,
                                        uint32_t& r2, uint32_t& r3, uint32_t a) {
    asm volatile("ldmatrix.sync.aligned.m8n8.x4.shared.b16 {%0,%1,%2,%3}, [%4];"
                 : "=r"(r0), "=r"(r1), "=r"(r2), "=r"(r3) : "r"(a));
}
__device__ __forceinline__ void mma_bf16(float* c, const uint32_t* a, const uint32_t* b) {
    asm volatile(
        "mma.sync.aligned.m16n8k16.row.col.f32.bf16.bf16.f32 "
        "{%0,%1,%2,%3}, {%4,%5,%6,%7}, {%8,%9}, {%0,%1,%2,%3};"
        : "+f"(c[0]), "+f"(c[1]), "+f"(c[2]), "+f"(c[3])
        : "r"(a[0]), "r"(a[1]), "r"(a[2]), "r"(a[3]), "r"(b[0]), "r"(b[1]));
}

// ---------------- table init ---------------------------------------------------
__global__ void init_tables() {
    int i = blockIdx.x * blockDim.x + threadIdx.x;
    const float TWO_PI = 6.283185307179586f;
    if (i < 512) {
        float a = TWO_PI * (float)i / 1024.0f;
        g_c1024[i] = cosf(a);
        g_s1024[i] = sinf(a);
    }
    if (i < 256) {
        float a = TWO_PI * (float)i / 512.0f;
        g_c512[i] = cosf(a);
        g_s512[i] = sinf(a);
    }
    if (i < 1024) {
        float w = 0.5f * (1.0f - cosf(TWO_PI * (float)i / 1024.0f));
        g_winS[i] = w * (1.0f / 1024.0f);
        g_win2[i] = w * w;
    }
}

// ---------------- split prep (2 terms) --------------------------------------------
__device__ __forceinline__ void split2(float v, __nv_bfloat16& h0, __nv_bfloat16& h1) {
    h0 = __float2bfloat16(v);
    h1 = __float2bfloat16(v - __bfloat162float(h0));
}

__global__ void split_x_kernel(const float* __restrict__ x) {
    __shared__ float tile[32][33];
    int b = blockIdx.z;
    int k0 = blockIdx.y * 32, t0 = blockIdx.x * 32;
    int tx = threadIdx.x, ty = threadIdx.y;
    const float* src = x + ((size_t)b * DIMK + k0) * TT + t0;
    #pragma unroll
    for (int r = 0; r < 4; r++)
        tile[ty + 8 * r][tx] = src[(size_t)(ty + 8 * r) * TT + tx];
    __syncthreads();
    #pragma unroll
    for (int r = 0; r < 4; r++) {
        float v = tile[tx][ty + 8 * r];
        size_t m = (size_t)b * TT + t0 + ty + 8 * r;
        __nv_bfloat16 h0, h1;
        split2(v, h0, h1);
        size_t o = m * DIMK + k0 + tx;
        g_A[o] = h0;
        g_A[ASZ + o] = h1;
    }
}

__global__ void split_w_kernel(const float* __restrict__ Wm,
                               const float* __restrict__ Wp) {
    int n = blockIdx.x;
    const float* src = (n < NBINS) ? Wm + (size_t)n * DIMK
                                   : Wp + (size_t)(n - NBINS) * DIMK;
    for (int k = threadIdx.x; k < DIMK; k += 256) {
        float v = src[k];
        __nv_bfloat16 h0, h1;
        split2(v, h0, h1);
        size_t o = (size_t)n * DIMK + k;
        g_B[o] = h0;
        g_B[BSZ + o] = h1;
    }
}

// ---------------- HMMA 2-split dual GEMM: 256x128 tile, 512 thr -------------------
__global__ void __launch_bounds__(NTHR, 1) gemm_hmma(
    const float* __restrict__ bmag, const float* __restrict__ bphs)
{
    extern __shared__ char smraw[];
    uint32_t smem_base = smem_u32(smraw);

    int tid = threadIdx.x;
    int lane = tid & 31, wid = tid >> 5;     // 16 warps
    int wm = wid >> 2, wn = wid & 3;         // 4 x 4 warp grid: 64m x 32n each
    int n0 = blockIdx.x * TLN;
    int m0 = blockIdx.y * TLM;

    float acc[4][4][4];
    #pragma unroll
    for (int mt = 0; mt < 4; mt++)
        #pragma unroll
        for (int nt = 0; nt < 4; nt++)
            #pragma unroll
            for (int r = 0; r < 4; r++) acc[mt][nt][r] = 0.f;

    uint32_t aoff = (uint32_t)((wm * 64 + (lane & 15)) * SROW + (lane >> 4) * 16);
    uint32_t boff = (uint32_t)((wn * 32 + (lane & 7) + (lane >> 4) * 8) * SROW +
                               ((lane >> 3) & 1) * 16);

    // 3072 cp16 per chunk -> 6 per thread
    // layout: v<2048 A (p=v>>10, row=(v&1023)>>2, ch=v&3); else B (p=..>>9,...)
    #define ISSUE_CHUNK(k0_, buf_) do {                                              \
        uint32_t stage_ = smem_base + (uint32_t)(buf_) * STAGE_BYTES;                 \
        _Pragma("unroll")                                                             \
        for (int i_ = 0; i_ < 6; i_++) {                                              \
            int v_ = tid + i_ * NTHR;                                                 \
            int isB_ = v_ >= 2048;                                                    \
            int r_ = isB_ ? v_ - 2048 : v_;                                           \
            int p_ = isB_ ? (r_ >> 9) : (r_ >> 10);                                   \
            int rem_ = isB_ ? (r_ & 511) : (r_ & 1023);                               \
            int row_ = rem_ >> 2;                                                     \
            int ch_ = rem_ & 3;                                                       \
            const __nv_bfloat16* s_ = isB_                                            \
                ? g_B + (size_t)p_ * BSZ + (size_t)(n0 + row_) * DIMK + (k0_) + ch_ * 8 \
                : g_A + (size_t)p_ * ASZ + (size_t)(m0 + row_) * DIMK + (k0_) + ch_ * 8; \
            uint32_t d_ = stage_ +                                                    \
                (isB_ ? (uint32_t)(B_BASE + p_ * B_SPLIT) : (uint32_t)(p_ * A_SPLIT)) \
                + (uint32_t)(row_ * SROW + ch_ * 16);                                 \
            cp16(d_, s_);                                                             \
        }                                                                             \
        CP_COMMIT();                                                                  \
    } while (0)

    ISSUE_CHUNK(0, 0);
    ISSUE_CHUNK(KC, 1);

    #pragma unroll 1
    for (int c = 0; c < NCHG; c++) {
        int s = c % NSTAGE;
        CP_WAIT1();
        __syncthreads();
        if (c + 2 < NCHG) ISSUE_CHUNK((c + 2) * KC, (c + 2) % NSTAGE);

        uint32_t sA = smem_base + (uint32_t)s * STAGE_BYTES;
        uint32_t sB = sA + B_BASE;

        #pragma unroll
        for (int ks = 0; ks < 2; ks++) {
            uint32_t afr[4][4];
            uint32_t bfr0[4][2], bfr1[4][2];

            // B fragments, both splits (16 regs)
            {
                uint32_t bd0 = sB + boff + (uint32_t)(ks * 32);
                ldsm_x4(bfr0[0][0], bfr0[0][1], bfr0[1][0], bfr0[1][1], bd0);
                ldsm_x4(bfr0[2][0], bfr0[2][1], bfr0[3][0], bfr0[3][1], bd0 + 16 * SROW);
                uint32_t bd1 = bd0 + B_SPLIT;
                ldsm_x4(bfr1[0][0], bfr1[0][1], bfr1[1][0], bfr1[1][1], bd1);
                ldsm_x4(bfr1[2][0], bfr1[2][1], bfr1[3][0], bfr1[3][1], bd1 + 16 * SROW);
            }
            // A split 0
            #pragma unroll
            for (int mt = 0; mt < 4; mt++) {
                uint32_t ad = sA + aoff + (uint32_t)(mt * 16 * SROW + ks * 32);
                ldsm_x4(afr[mt][0], afr[mt][1], afr[mt][2], afr[mt][3], ad);
            }
            #pragma unroll
            for (int mt = 0; mt < 4; mt++)
                #pragma unroll
                for (int nt = 0; nt < 4; nt++)
                    mma_bf16(acc[mt][nt], afr[mt], bfr0[nt]);   // A0*B0
            #pragma unroll
            for (int mt = 0; mt < 4; mt++)
                #pragma unroll
                for (int nt = 0; nt < 4; nt++)
                    mma_bf16(acc[mt][nt], afr[mt], bfr1[nt]);   // A0*B1
            // A split 1 (reuse afr regs)
            #pragma unroll
            for (int mt = 0; mt < 4; mt++) {
                uint32_t ad = sA + A_SPLIT + aoff + (uint32_t)(mt * 16 * SROW + ks * 32);
                ldsm_x4(afr[mt][0], afr[mt][1], afr[mt][2], afr[mt][3], ad);
            }
            #pragma unroll
            for (int mt = 0; mt < 4; mt++)
                #pragma unroll
                for (int nt = 0; nt < 4; nt++)
                    mma_bf16(acc[mt][nt], afr[mt], bfr0[nt]);   // A1*B0
        }
    }
    #undef ISSUE_CHUNK

    // epilogue
    const float PI_F = 3.14159265358979323846f;
    #pragma unroll
    for (int mt = 0; mt < 4; mt++) {
        #pragma unroll
        for (int nt = 0; nt < 4; nt++) {
            int r0 = m0 + wm * 64 + mt * 16 + (lane >> 2);
            int cg = n0 + wn * 32 + nt * 8 + (lane & 3) * 2;
            #pragma unroll
            for (int hh = 0; hh < 2; hh++) {
                int m = r0 + hh * 8;
                size_t row = (size_t)m * NBP;
                #pragma unroll
                for (int e = 0; e < 2; e++) {
                    int ng = cg + e;
                    float v = acc[mt][nt][hh * 2 + e];
                    if (ng < NBINS) {
                        v += __ldg(bmag + ng);
                        v = fminf(fmaxf(v, -10.f), 10.f);
                        g_mag[row + ng] = expf(v);
                    } else {
                        int nn = ng - NBINS;     // phase bins 0..510
                        v += __ldg(bphs + nn);
                        v = fminf(fmaxf(v, -PI_F), PI_F);
                        g_frq[row + nn] = v;
                    }
                }
            }
        }
    }
}

// ---------------- phase bins 511, 512: fp32 SIMT dot ---------------------------------
__global__ __launch_bounds__(256) void extra_bins_kernel(
    const float* __restrict__ x, const float* __restrict__ Wp,
    const float* __restrict__ bp)
{
    __shared__ float w0[1024];
    __shared__ float w1[1024];
    int tid = threadIdx.x;
    for (int k = tid; k < 1024; k += 256) {
        w0[k] = Wp[(size_t)511 * DIMK + k];
        w1[k] = Wp[(size_t)512 * DIMK + k];
    }
    __syncthreads();

    int t = blockIdx.x * 256 + tid;
    int b = blockIdx.y;
    const float* xb = x + (size_t)b * DIMK * TT + t;
    float a0 = 0.f, a1 = 0.f;
    #pragma unroll 8
    for (int k = 0; k < DIMK; k++) {
        float xv = xb[(size_t)k * TT];
        a0 = fmaf(xv, w0[k], a0);
        a1 = fmaf(xv, w1[k], a1);
    }
    const float PI_F = 3.14159265358979323846f;
    size_t row = (size_t)(b * TT + t) * NBP;
    g_frq[row + 511] = fminf(fmaxf(a0 + bp[511], -PI_F), PI_F);
    g_frq[row + 512] = fminf(fmaxf(a1 + bp[512], -PI_F), PI_F);
}

// ---------------- cumsum along time (in place) ----------------------------------------
__global__ void cumsum_kernel() {
    int n = blockIdx.x * 128 + threadIdx.x;
    int b = blockIdx.y;
    if (n >= NBINS) return;
    size_t base = (size_t)b * TT * NBP + n;
    float acc = 0.f;
    #pragma unroll 8
    for (int t = 0; t < TT; t++) {
        size_t off = base + (size_t)t * NBP;
        acc += g_frq[off];
        g_frq[off] = acc;
    }
}

// ---------------- frames: real irfft(1024) via 512-pt complex IFFT ---------------------
__global__ __launch_bounds__(128) void frames_kernel() {
    __shared__ float sxr[513];
    __shared__ float sxi[513];
    __shared__ float wre[512];
    __shared__ float wim[512];
    __shared__ float twr[256];
    __shared__ float twi[256];

    int f = blockIdx.x;
    int tid = threadIdx.x;
    size_t base = (size_t)f * NBP;

    for (int i = tid; i < 256; i += 128) {
        twr[i] = g_c512[i];
        twi[i] = g_s512[i];
    }
    for (int n = tid; n < 513; n += 128) {
        float mg = g_mag[base + n];
        float ph = g_frq[base + n];
        float s, c;
        sincosf(ph, &s, &c);
        float im = mg * s;
        if (n == 0 || n == 512) im = 0.f;
        sxr[n] = mg * c;
        sxi[n] = im;
    }
    __syncthreads();

    #pragma unroll
    for (int q = 0; q < 4; q++) {
        int k = tid + q * 128;
        int j = __brev((unsigned)k) >> 23;
        float x0r = sxr[j],       x0i = sxi[j];
        float x1r = sxr[512 - j], x1i = sxi[512 - j];
        float ar = x0r + x1r, ai = x0i - x1i;
        float br = x0r - x1r, bi = x0i + x1i;
        float tr = g_c1024[j], ti = g_s1024[j];
        wre[k] = ar - (tr * bi + ti * br);
        wim[k] = ai + (tr * br - ti * bi);
    }
    __syncthreads();

    #pragma unroll
    for (int p = 0; p < 4; p++) {
        int h = 1 << (2 * p);
        int lm = h - 1;
        int bi_ = ((tid >> (2 * p)) << (2 * p + 2)) | (tid & lm);
        int k1 = (tid & lm) << (8 - 2 * p);
        int k2 = k1 >> 1;

        float x0r = wre[bi_],         x0i = wim[bi_];
        float x1r = wre[bi_ + h],     x1i = wim[bi_ + h];
        float x2r = wre[bi_ + 2 * h], x2i = wim[bi_ + 2 * h];
        float x3r = wre[bi_ + 3 * h], x3i = wim[bi_ + 3 * h];

        float w1r = twr[k1], w1i = twi[k1];
        float t1r = x1r * w1r - x1i * w1i;
        float t1i = x1r * w1i + x1i * w1r;
        float a0r = x0r + t1r, a0i = x0i + t1i;
        float a1r = x0r - t1r, a1i = x0i - t1i;
        float t2r = x3r * w1r - x3i * w1i;
        float t2i = x3r * w1i + x3i * w1r;
        float a2r = x2r + t2r, a2i = x2i + t2i;
        float a3r = x2r - t2r, a3i = x2i - t2i;

        float w2r = twr[k2], w2i = twi[k2];
        float u0r = a2r * w2r - a2i * w2i;
        float u0i = a2r * w2i + a2i * w2r;
        float cr  = a3r * w2r - a3i * w2i;
        float ci  = a3r * w2i + a3i * w2r;
        float u1r = -ci, u1i = cr;

        __syncthreads();
        wre[bi_] = a0r + u0r;         wim[bi_] = a0i + u0i;
        wre[bi_ + h] = a1r + u1r;     wim[bi_ + h] = a1i + u1i;
        wre[bi_ + 2 * h] = a0r - u0r; wim[bi_ + 2 * h] = a0i - u0i;
        wre[bi_ + 3 * h] = a1r - u1r; wim[bi_ + 3 * h] = a1i - u1i;
        __syncthreads();
    }

    size_t ob = (size_t)f * NFFT;
    #pragma unroll
    for (int uu = 0; uu < 2; uu++) {
        int u = tid + uu * 128;
        float wr = twr[u], wi = twi[u];
        float ar = wre[u],       ai = wim[u];
        float br = wre[u + 256], bi = wim[u + 256];
        float tr = br * wr - bi * wi;
        float ti = br * wi + bi * wr;
        float y0r = ar + tr, y0i = ai + ti;
        float y1r = ar - tr, y1i = ai - ti;
        float2 o0 = make_float2(y0r * g_winS[2 * u], y0i * g_winS[2 * u + 1]);
        float2 o1 = make_float2(y1r * g_winS[2 * u + 512], y1i * g_winS[2 * u + 513]);
        *reinterpret_cast<float2*>(&g_frames[ob + 2 * u]) = o0;
        *reinterpret_cast<float2*>(&g_frames[ob + 2 * u + 512]) = o1;
    }
}

// ---------------- overlap-add -----------------------------------------------------------
__global__ void oa_kernel(float* __restrict__ out) {
    int idx = blockIdx.x * 256 + threadIdx.x;
    if (idx >= BATCH * OUTLEN) return;
    int b = idx / OUTLEN;
    int s = idx - b * OUTLEN;
    int p = s + NFFT / 2;

    int t1 = p >> 8;  if (t1 > TT - 1) t1 = TT - 1;
    int t0 = (p >= NFFT - HOP) ? ((p - (NFFT - HOP)) >> 8) : 0;

    float sig = 0.f, env = 0.f;
    #pragma unroll 4
    for (int t = t0; t <= t1; t++) {
        int j = p - (t << 8);
        sig += g_frames[((size_t)(b * TT + t) << 10) + j];
        env += g_win2[j];
    }
    float v = sig / env;
    out[idx] = fminf(fmaxf(v, -1.f), 1.f);
}

// ---------------- launcher ----------------------------------------------------------------
extern "C" void kernel_launch(void* const* d_in, const int* in_sizes, int n_in,
                              void* d_out, int out_size) {
    (void)in_sizes; (void)n_in; (void)out_size;
    const float* x  = (const float*)d_in[0];
    const float* Wm = (const float*)d_in[1];
    const float* bm = (const float*)d_in[2];
    const float* Wp = (const float*)d_in[3];
    const float* bp = (const float*)d_in[4];
    float* out = (float*)d_out;

    cudaFuncSetAttribute(gemm_hmma, cudaFuncAttributeMaxDynamicSharedMemorySize,
                         GEMM_SMEM);

    init_tables<<<4, 256>>>();
    split_x_kernel<<<dim3(TT / 32, DIMK / 32, BATCH), dim3(32, 8)>>>(x);
    split_w_kernel<<<NPAD, 256>>>(Wm, Wp);

    gemm_hmma<<<dim3(NPAD / TLN, MTOT / TLM), NTHR, GEMM_SMEM>>>(bm, bp);
    extra_bins_kernel<<<dim3(TT / 256, BATCH), 256>>>(x, Wp, bp);

    cumsum_kernel<<<dim3(5, BATCH), 128>>>();
    frames_kernel<<<MTOT, 128>>>();
    oa_kernel<<<(BATCH * OUTLEN + 255) / 256, 256>>>(out);
}

// round 7
// speedup vs baseline: 1.8812x; 1.0677x over previous
#include <cuda_runtime.h>
#include <cuda_bf16.h>
#include <math.h>
#include <cstdint>

#define BATCH 16
#define DIMK  1024
#define TT    2048
#define NFFT  1024
#define HOP   256
#define NBINS 513
#define NBP   520
#define MTOT  (BATCH * TT)          // 32768
#define OUTLEN (HOP * (TT - 1))     // 524032

#define NPAD  1024                  // 8 n-tiles; bins 511/512 (phase) via SIMT
#define TLM   256
#define TLN   128
#define KC    64
#define NCHG  (DIMK / KC)           // 16
#define NSPLIT 2
#define NTHR  512

static constexpr size_t ASZ = (size_t)MTOT * DIMK;
static constexpr size_t BSZ = (size_t)NPAD * DIMK;

// smem: rows of 128B data + 16B pad (conflict-free: 144 mod 128 = 16)
#define SROW        144
#define A_SPLIT     (256 * SROW)              // 36864
#define B_SPLIT     (128 * SROW)              // 18432
#define B_BASE      (2 * A_SPLIT)             // 73728
#define STAGE_BYTES (2 * A_SPLIT + 2 * B_SPLIT)  // 110592
#define NSTAGE      2
#define GEMM_SMEM   (NSTAGE * STAGE_BYTES)    // 221184

// ---------------- scratch ----------------------------------------------------
__device__ __nv_bfloat16 g_A[(size_t)NSPLIT * ASZ];
__device__ __nv_bfloat16 g_B[(size_t)NSPLIT * BSZ];
__device__ float g_mag[(size_t)MTOT * NBP];
__device__ float g_frq[(size_t)MTOT * NBP];
__device__ float g_frames[(size_t)MTOT * NFFT];
__device__ float g_c1024[512];
__device__ float g_s1024[512];
__device__ float g_c512[256];
__device__ float g_s512[256];
__device__ float g_winS[1024];
__device__ float g_win2[1024];

// ---------------- helpers -----------------------------------------------------
__device__ __forceinline__ uint32_t smem_u32(const void* p) {
    uint32_t a;
    asm("{ .reg .u64 t; cvta.to.shared.u64 t, %1; cvt.u32.u64 %0, t; }"
        : "=r"(a) : "l"(p));
    return a;
}
__device__ __forceinline__ void cp16(uint32_t dst, const void* src) {
    asm volatile("cp.async.cg.shared.global [%0], [%1], 16;" :: "r"(dst), "l"(src));
}
#define CP_COMMIT() asm volatile("cp.async.commit_group;")
#define CP_WAIT0()  asm volatile("cp.async.wait_group 0;" ::: "memory")

__device__ __forceinline__ void ldsm_x4(uint32_t& r0, uint32_t& r1,
                                        uint32_t& r2, uint32_t& r3, uint32_t a) {
    asm volatile("ldmatrix.sync.aligned.m8n8.x4.shared.b16 {%0,%1,%2,%3}, [%4];"
                 : "=r"(r0), "=r"(r1), "=r"(r2), "=r"(r3) : "r"(a));
}
__device__ __forceinline__ void mma_bf16(float* c, const uint32_t* a, const uint32_t* b) {
    asm volatile(
        "mma.sync.aligned.m16n8k16.row.col.f32.bf16.bf16.f32 "
        "{%0,%1,%2,%3}, {%4,%5,%6,%7}, {%8,%9}, {%0,%1,%2,%3};"
        : "+f"(c[0]), "+f"(c[1]), "+f"(c[2]), "+f"(c[3])
        : "r"(a[0]), "r"(a[1]), "r"(a[2]), "r"(a[3]), "r"(b[0]), "r"(b[1]));
}

// ---------------- table init ---------------------------------------------------
__global__ void init_tables() {
    int i = blockIdx.x * blockDim.x + threadIdx.x;
    const float TWO_PI = 6.283185307179586f;
    if (i < 512) {
        float a = TWO_PI * (float)i / 1024.0f;
        g_c1024[i] = cosf(a);
        g_s1024[i] = sinf(a);
    }
    if (i < 256) {
        float a = TWO_PI * (float)i / 512.0f;
        g_c512[i] = cosf(a);
        g_s512[i] = sinf(a);
    }
    if (i < 1024) {
        float w = 0.5f * (1.0f - cosf(TWO_PI * (float)i / 1024.0f));
        g_winS[i] = w * (1.0f / 1024.0f);
        g_win2[i] = w * w;
    }
}

// ---------------- split prep (2 terms) --------------------------------------------
__device__ __forceinline__ void split2(float v, __nv_bfloat16& h0, __nv_bfloat16& h1) {
    h0 = __float2bfloat16(v);
    h1 = __float2bfloat16(v - __bfloat162float(h0));
}

__global__ void split_x_kernel(const float* __restrict__ x) {
    __shared__ float tile[32][33];
    int b = blockIdx.z;
    int k0 = blockIdx.y * 32, t0 = blockIdx.x * 32;
    int tx = threadIdx.x, ty = threadIdx.y;
    const float* src = x + ((size_t)b * DIMK + k0) * TT + t0;
    #pragma unroll
    for (int r = 0; r < 4; r++)
        tile[ty + 8 * r][tx] = src[(size_t)(ty + 8 * r) * TT + tx];
    __syncthreads();
    #pragma unroll
    for (int r = 0; r < 4; r++) {
        float v = tile[tx][ty + 8 * r];
        size_t m = (size_t)b * TT + t0 + ty + 8 * r;
        __nv_bfloat16 h0, h1;
        split2(v, h0, h1);
        size_t o = m * DIMK + k0 + tx;
        g_A[o] = h0;
        g_A[ASZ + o] = h1;
    }
}

__global__ void split_w_kernel(const float* __restrict__ Wm,
                               const float* __restrict__ Wp) {
    int n = blockIdx.x;
    const float* src = (n < NBINS) ? Wm + (size_t)n * DIMK
                                   : Wp + (size_t)(n - NBINS) * DIMK;
    for (int k = threadIdx.x; k < DIMK; k += 256) {
        float v = src[k];
        __nv_bfloat16 h0, h1;
        split2(v, h0, h1);
        size_t o = (size_t)n * DIMK + k;
        g_B[o] = h0;
        g_B[BSZ + o] = h1;
    }
}

// ---------------- HMMA 2-split dual GEMM: 256x128, KC=64, 2-stage ------------------
__global__ void __launch_bounds__(NTHR, 1) gemm_hmma(
    const float* __restrict__ bmag, const float* __restrict__ bphs)
{
    extern __shared__ char smraw[];
    uint32_t smem_base = smem_u32(smraw);

    int tid = threadIdx.x;
    int lane = tid & 31, wid = tid >> 5;     // 16 warps: 4x4, 64m x 32n each
    int wm = wid >> 2, wn = wid & 3;
    int n0 = blockIdx.x * TLN;
    int m0 = blockIdx.y * TLM;

    float acc[4][4][4];
    #pragma unroll
    for (int mt = 0; mt < 4; mt++)
        #pragma unroll
        for (int nt = 0; nt < 4; nt++)
            #pragma unroll
            for (int r = 0; r < 4; r++) acc[mt][nt][r] = 0.f;

    uint32_t aoff = (uint32_t)((wm * 64 + (lane & 15)) * SROW + (lane >> 4) * 16);
    uint32_t boff = (uint32_t)((wn * 32 + (lane & 7) + (lane >> 4) * 8) * SROW +
                               ((lane >> 3) & 1) * 16);

    // 6144 cp16 per chunk -> 12 per thread -> 4 parts of 3
    // v < 4096: A (p=v>>11, row=(v&2047)>>3, ch=v&7); else B (p=r>>10, ...)
    #define ISSUE_PART(k0_, buf_, part_) do {                                         \
        uint32_t stage_ = smem_base + (uint32_t)(buf_) * STAGE_BYTES;                 \
        _Pragma("unroll")                                                             \
        for (int j_ = 0; j_ < 3; j_++) {                                              \
            int v_ = tid + ((part_) * 3 + j_) * NTHR;                                 \
            int isB_ = v_ >= 4096;                                                    \
            int r_ = isB_ ? v_ - 4096 : v_;                                           \
            int p_ = isB_ ? (r_ >> 10) : (r_ >> 11);                                  \
            int rem_ = isB_ ? (r_ & 1023) : (r_ & 2047);                              \
            int row_ = rem_ >> 3;                                                     \
            int ch_ = rem_ & 7;                                                       \
            const __nv_bfloat16* s_ = isB_                                            \
                ? g_B + (size_t)p_ * BSZ + (size_t)(n0 + row_) * DIMK + (k0_) + ch_ * 8 \
                : g_A + (size_t)p_ * ASZ + (size_t)(m0 + row_) * DIMK + (k0_) + ch_ * 8; \
            uint32_t d_ = stage_ +                                                    \
                (isB_ ? (uint32_t)(B_BASE + p_ * B_SPLIT) : (uint32_t)(p_ * A_SPLIT)) \
                + (uint32_t)(row_ * SROW + ch_ * 16);                                 \
            cp16(d_, s_);                                                             \
        }                                                                             \
    } while (0)

    // prologue: chunk 0 -> buf 0
    ISSUE_PART(0, 0, 0);
    ISSUE_PART(0, 0, 1);
    ISSUE_PART(0, 0, 2);
    ISSUE_PART(0, 0, 3);
    CP_COMMIT();

    #pragma unroll 1
    for (int c = 0; c < NCHG; c++) {
        int s = c & 1;
        CP_WAIT0();
        __syncthreads();

        uint32_t sA = smem_base + (uint32_t)s * STAGE_BYTES;
        uint32_t sB = sA + B_BASE;
        int knext = (c + 1) * KC;
        bool more = (c + 1 < NCHG);

        #pragma unroll
        for (int ks = 0; ks < 4; ks++) {
            uint32_t afr[4][4];
            uint32_t bfr0[4][2], bfr1[4][2];

            // B fragments, both splits
            {
                uint32_t bd0 = sB + boff + (uint32_t)(ks * 32);
                ldsm_x4(bfr0[0][0], bfr0[0][1], bfr0[1][0], bfr0[1][1], bd0);
                ldsm_x4(bfr0[2][0], bfr0[2][1], bfr0[3][0], bfr0[3][1], bd0 + 16 * SROW);
                uint32_t bd1 = bd0 + B_SPLIT;
                ldsm_x4(bfr1[0][0], bfr1[0][1], bfr1[1][0], bfr1[1][1], bd1);
                ldsm_x4(bfr1[2][0], bfr1[2][1], bfr1[3][0], bfr1[3][1], bd1 + 16 * SROW);
            }
            // A split 0
            #pragma unroll
            for (int mt = 0; mt < 4; mt++) {
                uint32_t ad = sA + aoff + (uint32_t)(mt * 16 * SROW + ks * 32);
                ldsm_x4(afr[mt][0], afr[mt][1], afr[mt][2], afr[mt][3], ad);
            }

            // interleave this kstep's share of next chunk's loads
            if (more) {
                if (ks == 0)      ISSUE_PART(knext, s ^ 1, 0);
                else if (ks == 1) ISSUE_PART(knext, s ^ 1, 1);
                else if (ks == 2) ISSUE_PART(knext, s ^ 1, 2);
            }

            #pragma unroll
            for (int mt = 0; mt < 4; mt++)
                #pragma unroll
                for (int nt = 0; nt < 4; nt++)
                    mma_bf16(acc[mt][nt], afr[mt], bfr0[nt]);   // A0*B0
            #pragma unroll
            for (int mt = 0; mt < 4; mt++)
                #pragma unroll
                for (int nt = 0; nt < 4; nt++)
                    mma_bf16(acc[mt][nt], afr[mt], bfr1[nt]);   // A0*B1
            // A split 1 (reuse afr regs)
            #pragma unroll
            for (int mt = 0; mt < 4; mt++) {
                uint32_t ad = sA + A_SPLIT + aoff + (uint32_t)(mt * 16 * SROW + ks * 32);
                ldsm_x4(afr[mt][0], afr[mt][1], afr[mt][2], afr[mt][3], ad);
            }
            if (more && ks == 3) ISSUE_PART(knext, s ^ 1, 3);
            #pragma unroll
            for (int mt = 0; mt < 4; mt++)
                #pragma unroll
                for (int nt = 0; nt < 4; nt++)
                    mma_bf16(acc[mt][nt], afr[mt], bfr0[nt]);   // A1*B0
        }
        if (more) CP_COMMIT();
    }
    #undef ISSUE_PART

    // epilogue
    const float PI_F = 3.14159265358979323846f;
    #pragma unroll
    for (int mt = 0; mt < 4; mt++) {
        #pragma unroll
        for (int nt = 0; nt < 4; nt++) {
            int r0 = m0 + wm * 64 + mt * 16 + (lane >> 2);
            int cg = n0 + wn * 32 + nt * 8 + (lane & 3) * 2;
            #pragma unroll
            for (int hh = 0; hh < 2; hh++) {
                int m = r0 + hh * 8;
                size_t row = (size_t)m * NBP;
                #pragma unroll
                for (int e = 0; e < 2; e++) {
                    int ng = cg + e;
                    float v = acc[mt][nt][hh * 2 + e];
                    if (ng < NBINS) {
                        v += __ldg(bmag + ng);
                        v = fminf(fmaxf(v, -10.f), 10.f);
                        g_mag[row + ng] = expf(v);
                    } else {
                        int nn = ng - NBINS;     // phase bins 0..510
                        v += __ldg(bphs + nn);
                        v = fminf(fmaxf(v, -PI_F), PI_F);
                        g_frq[row + nn] = v;
                    }
                }
            }
        }
    }
}

// ---------------- phase bins 511, 512: fp32 SIMT dot ---------------------------------
__global__ __launch_bounds__(256) void extra_bins_kernel(
    const float* __restrict__ x, const float* __restrict__ Wp,
    const float* __restrict__ bp)
{
    __shared__ float w0[1024];
    __shared__ float w1[1024];
    int tid = threadIdx.x;
    for (int k = tid; k < 1024; k += 256) {
        w0[k] = Wp[(size_t)511 * DIMK + k];
        w1[k] = Wp[(size_t)512 * DIMK + k];
    }
    __syncthreads();

    int t = blockIdx.x * 256 + tid;
    int b = blockIdx.y;
    const float* xb = x + (size_t)b * DIMK * TT + t;
    float a0 = 0.f, a1 = 0.f;
    #pragma unroll 8
    for (int k = 0; k < DIMK; k++) {
        float xv = xb[(size_t)k * TT];
        a0 = fmaf(xv, w0[k], a0);
        a1 = fmaf(xv, w1[k], a1);
    }
    const float PI_F = 3.14159265358979323846f;
    size_t row = (size_t)(b * TT + t) * NBP;
    g_frq[row + 511] = fminf(fmaxf(a0 + bp[511], -PI_F), PI_F);
    g_frq[row + 512] = fminf(fmaxf(a1 + bp[512], -PI_F), PI_F);
}

// ---------------- cumsum along time (in place) ----------------------------------------
__global__ void cumsum_kernel() {
    int n = blockIdx.x * 128 + threadIdx.x;
    int b = blockIdx.y;
    if (n >= NBINS) return;
    size_t base = (size_t)b * TT * NBP + n;
    float acc = 0.f;
    #pragma unroll 8
    for (int t = 0; t < TT; t++) {
        size_t off = base + (size_t)t * NBP;
        acc += g_frq[off];
        g_frq[off] = acc;
    }
}

// ---------------- frames: real irfft(1024) via 512-pt complex IFFT ---------------------
__global__ __launch_bounds__(128) void frames_kernel() {
    __shared__ float sxr[513];
    __shared__ float sxi[513];
    __shared__ float wre[512];
    __shared__ float wim[512];
    __shared__ float twr[256];
    __shared__ float twi[256];

    int f = blockIdx.x;
    int tid = threadIdx.x;
    size_t base = (size_t)f * NBP;

    for (int i = tid; i < 256; i += 128) {
        twr[i] = g_c512[i];
        twi[i] = g_s512[i];
    }
    for (int n = tid; n < 513; n += 128) {
        float mg = g_mag[base + n];
        float ph = g_frq[base + n];
        float s, c;
        sincosf(ph, &s, &c);
        float im = mg * s;
        if (n == 0 || n == 512) im = 0.f;
        sxr[n] = mg * c;
        sxi[n] = im;
    }
    __syncthreads();

    #pragma unroll
    for (int q = 0; q < 4; q++) {
        int k = tid + q * 128;
        int j = __brev((unsigned)k) >> 23;
        float x0r = sxr[j],       x0i = sxi[j];
        float x1r = sxr[512 - j], x1i = sxi[512 - j];
        float ar = x0r + x1r, ai = x0i - x1i;
        float br = x0r - x1r, bi = x0i + x1i;
        float tr = g_c1024[j], ti = g_s1024[j];
        wre[k] = ar - (tr * bi + ti * br);
        wim[k] = ai + (tr * br - ti * bi);
    }
    __syncthreads();

    #pragma unroll
    for (int p = 0; p < 4; p++) {
        int h = 1 << (2 * p);
        int lm = h - 1;
        int bi_ = ((tid >> (2 * p)) << (2 * p + 2)) | (tid & lm);
        int k1 = (tid & lm) << (8 - 2 * p);
        int k2 = k1 >> 1;

        float x0r = wre[bi_],         x0i = wim[bi_];
        float x1r = wre[bi_ + h],     x1i = wim[bi_ + h];
        float x2r = wre[bi_ + 2 * h], x2i = wim[bi_ + 2 * h];
        float x3r = wre[bi_ + 3 * h], x3i = wim[bi_ + 3 * h];

        float w1r = twr[k1], w1i = twi[k1];
        float t1r = x1r * w1r - x1i * w1i;
        float t1i = x1r * w1i + x1i * w1r;
        float a0r = x0r + t1r, a0i = x0i + t1i;
        float a1r = x0r - t1r, a1i = x0i - t1i;
        float t2r = x3r * w1r - x3i * w1i;
        float t2i = x3r * w1i + x3i * w1r;
        float a2r = x2r + t2r, a2i = x2i + t2i;
        float a3r = x2r - t2r, a3i = x2i - t2i;

        float w2r = twr[k2], w2i = twi[k2];
        float u0r = a2r * w2r - a2i * w2i;
        float u0i = a2r * w2i + a2i * w2r;
        float cr  = a3r * w2r - a3i * w2i;
        float ci  = a3r * w2i + a3i * w2r;
        float u1r = -ci, u1i = cr;

        __syncthreads();
        wre[bi_] = a0r + u0r;         wim[bi_] = a0i + u0i;
        wre[bi_ + h] = a1r + u1r;     wim[bi_ + h] = a1i + u1i;
        wre[bi_ + 2 * h] = a0r - u0r; wim[bi_ + 2 * h] = a0i - u0i;
        wre[bi_ + 3 * h] = a1r - u1r; wim[bi_ + 3 * h] = a1i - u1i;
        __syncthreads();
    }

    size_t ob = (size_t)f * NFFT;
    #pragma unroll
    for (int uu = 0; uu < 2; uu++) {
        int u = tid + uu * 128;
        float wr = twr[u], wi = twi[u];
        float ar = wre[u],       ai = wim[u];
        float br = wre[u + 256], bi = wim[u + 256];
        float tr = br * wr - bi * wi;
        float ti = br * wi + bi * wr;
        float y0r = ar + tr, y0i = ai + ti;
        float y1r = ar - tr, y1i = ai - ti;
        float2 o0 = make_float2(y0r * g_winS[2 * u], y0i * g_winS[2 * u + 1]);
        float2 o1 = make_float2(y1r * g_winS[2 * u + 512], y1i * g_winS[2 * u + 513]);
        *reinterpret_cast<float2*>(&g_frames[ob + 2 * u]) = o0;
        *reinterpret_cast<float2*>(&g_frames[ob + 2 * u + 512]) = o1;
    }
}

// ---------------- overlap-add -----------------------------------------------------------
__global__ void oa_kernel(float* __restrict__ out) {
    int idx = blockIdx.x * 256 + threadIdx.x;
    if (idx >= BATCH * OUTLEN) return;
    int b = idx / OUTLEN;
    int s = idx - b * OUTLEN;
    int p = s + NFFT / 2;

    int t1 = p >> 8;  if (t1 > TT - 1) t1 = TT - 1;
    int t0 = (p >= NFFT - HOP) ? ((p - (NFFT - HOP)) >> 8) : 0;

    float sig = 0.f, env = 0.f;
    #pragma unroll 4
    for (int t = t0; t <= t1; t++) {
        int j = p - (t << 8);
        sig += g_frames[((size_t)(b * TT + t) << 10) + j];
        env += g_win2[j];
    }
    float v = sig / env;
    out[idx] = fminf(fmaxf(v, -1.f), 1.f);
}

// ---------------- launcher ----------------------------------------------------------------
extern "C" void kernel_launch(void* const* d_in, const int* in_sizes, int n_in,
                              void* d_out, int out_size) {
    (void)in_sizes; (void)n_in; (void)out_size;
    const float* x  = (const float*)d_in[0];
    const float* Wm = (const float*)d_in[1];
    const float* bm = (const float*)d_in[2];
    const float* Wp = (const float*)d_in[3];
    const float* bp = (const float*)d_in[4];
    float* out = (float*)d_out;

    cudaFuncSetAttribute(gemm_hmma, cudaFuncAttributeMaxDynamicSharedMemorySize,
                         GEMM_SMEM);

    init_tables<<<4, 256>>>();
    split_x_kernel<<<dim3(TT / 32, DIMK / 32, BATCH), dim3(32, 8)>>>(x);
    split_w_kernel<<<NPAD, 256>>>(Wm, Wp);

    gemm_hmma<<<dim3(NPAD / TLN, MTOT / TLM), NTHR, GEMM_SMEM>>>(bm, bp);
    extra_bins_kernel<<<dim3(TT / 256, BATCH), 256>>>(x, Wp, bp);

    cumsum_kernel<<<dim3(5, BATCH), 128>>>();
    frames_kernel<<<MTOT, 128>>>();
    oa_kernel<<<(BATCH * OUTLEN + 255) / 256, 256>>>(out);
}

// round 8
// speedup vs baseline: 2.1550x; 1.1455x over previous
#include <cuda_runtime.h>
#include <cuda_bf16.h>
#include <math.h>
#include <cstdint>

#define BATCH 16
#define DIMK  1024
#define TT    2048
#define NFFT  1024
#define HOP   256
#define NBINS 513
#define NBP   520
#define MTOT  (BATCH * TT)          // 32768
#define OUTLEN (HOP * (TT - 1))     // 524032

#define NPAD  1024                  // 8 n-tiles; bins 511/512 (phase) via SIMT
#define TLM   256
#define TLN   128
#define KC    64
#define NCHG  (DIMK / KC)           // 16
#define NSPLIT 2
#define NTHR  512

#define TSEG  256
#define NSEG  (TT / TSEG)           // 8

static constexpr size_t ASZ = (size_t)MTOT * DIMK;
static constexpr size_t BSZ = (size_t)NPAD * DIMK;

// smem: rows of 128B data + 16B pad (conflict-free: 144 mod 128 = 16)
#define SROW        144
#define A_SPLIT     (256 * SROW)              // 36864
#define B_SPLIT     (128 * SROW)              // 18432
#define B_BASE      (2 * A_SPLIT)             // 73728
#define STAGE_BYTES (2 * A_SPLIT + 2 * B_SPLIT)  // 110592
#define NSTAGE      2
#define GEMM_SMEM   (NSTAGE * STAGE_BYTES)    // 221184

// ---------------- scratch ----------------------------------------------------
__device__ __nv_bfloat16 g_A[(size_t)NSPLIT * ASZ];
__device__ __nv_bfloat16 g_B[(size_t)NSPLIT * BSZ];
__device__ float g_mag[(size_t)MTOT * NBP];
__device__ float g_frq[(size_t)MTOT * NBP];
__device__ float g_frames[(size_t)MTOT * NFFT];
__device__ float g_segsum[BATCH][NSEG][NBP];
__device__ float g_c1024[512];
__device__ float g_s1024[512];
__device__ float g_c512[256];
__device__ float g_s512[256];
__device__ float g_winS[1024];
__device__ float g_win2[1024];

// ---------------- helpers -----------------------------------------------------
__device__ __forceinline__ uint32_t smem_u32(const void* p) {
    uint32_t a;
    asm("{ .reg .u64 t; cvta.to.shared.u64 t, %1; cvt.u32.u64 %0, t; }"
        : "=r"(a) : "l"(p));
    return a;
}
__device__ __forceinline__ void cp16(uint32_t dst, const void* src) {
    asm volatile("cp.async.cg.shared.global [%0], [%1], 16;" :: "r"(dst), "l"(src));
}
#define CP_COMMIT() asm volatile("cp.async.commit_group;")
#define CP_WAIT0()  asm volatile("cp.async.wait_group 0;" ::: "memory")

__device__ __forceinline__ void ldsm_x4(uint32_t& r0, uint32_t& r1,
                                        uint32_t& r2, uint32_t& r3, uint32_t a) {
    asm volatile("ldmatrix.sync.aligned.m8n8.x4.shared.b16 {%0,%1,%2,%3}, [%4];"
                 : "=r"(r0), "=r"(r1), "=r"(r2), "=r"(r3) : "r"(a));
}
__device__ __forceinline__ void mma_bf16(float* c, const uint32_t* a, const uint32_t* b) {
    asm volatile(
        "mma.sync.aligned.m16n8k16.row.col.f32.bf16.bf16.f32 "
        "{%0,%1,%2,%3}, {%4,%5,%6,%7}, {%8,%9}, {%0,%1,%2,%3};"
        : "+f"(c[0]), "+f"(c[1]), "+f"(c[2]), "+f"(c[3])
        : "r"(a[0]), "r"(a[1]), "r"(a[2]), "r"(a[3]), "r"(b[0]), "r"(b[1]));
}

// ---------------- table init ---------------------------------------------------
__global__ void init_tables() {
    int i = blockIdx.x * blockDim.x + threadIdx.x;
    const float TWO_PI = 6.283185307179586f;
    if (i < 512) {
        float a = TWO_PI * (float)i / 1024.0f;
        g_c1024[i] = cosf(a);
        g_s1024[i] = sinf(a);
    }
    if (i < 256) {
        float a = TWO_PI * (float)i / 512.0f;
        g_c512[i] = cosf(a);
        g_s512[i] = sinf(a);
    }
    if (i < 1024) {
        float w = 0.5f * (1.0f - cosf(TWO_PI * (float)i / 1024.0f));
        g_winS[i] = w * (1.0f / 1024.0f);
        g_win2[i] = w * w;
    }
}

// ---------------- split prep (2 terms) --------------------------------------------
__device__ __forceinline__ void split2(float v, __nv_bfloat16& h0, __nv_bfloat16& h1) {
    h0 = __float2bfloat16(v);
    h1 = __float2bfloat16(v - __bfloat162float(h0));
}

__global__ void split_x_kernel(const float* __restrict__ x) {
    __shared__ float tile[32][33];
    int b = blockIdx.z;
    int k0 = blockIdx.y * 32, t0 = blockIdx.x * 32;
    int tx = threadIdx.x, ty = threadIdx.y;
    const float* src = x + ((size_t)b * DIMK + k0) * TT + t0;
    #pragma unroll
    for (int r = 0; r < 4; r++)
        tile[ty + 8 * r][tx] = src[(size_t)(ty + 8 * r) * TT + tx];
    __syncthreads();
    #pragma unroll
    for (int r = 0; r < 4; r++) {
        float v = tile[tx][ty + 8 * r];
        size_t m = (size_t)b * TT + t0 + ty + 8 * r;
        __nv_bfloat16 h0, h1;
        split2(v, h0, h1);
        size_t o = m * DIMK + k0 + tx;
        g_A[o] = h0;
        g_A[ASZ + o] = h1;
    }
}

__global__ void split_w_kernel(const float* __restrict__ Wm,
                               const float* __restrict__ Wp) {
    int n = blockIdx.x;
    const float* src = (n < NBINS) ? Wm + (size_t)n * DIMK
                                   : Wp + (size_t)(n - NBINS) * DIMK;
    for (int k = threadIdx.x; k < DIMK; k += 256) {
        float v = src[k];
        __nv_bfloat16 h0, h1;
        split2(v, h0, h1);
        size_t o = (size_t)n * DIMK + k;
        g_B[o] = h0;
        g_B[BSZ + o] = h1;
    }
}

// ---------------- HMMA 2-split dual GEMM: 256x128, KC=64, 2-stage ------------------
__global__ void __launch_bounds__(NTHR, 1) gemm_hmma(
    const float* __restrict__ bmag, const float* __restrict__ bphs)
{
    extern __shared__ char smraw[];
    uint32_t smem_base = smem_u32(smraw);

    int tid = threadIdx.x;
    int lane = tid & 31, wid = tid >> 5;     // 16 warps: 4x4, 64m x 32n each
    int wm = wid >> 2, wn = wid & 3;
    int n0 = blockIdx.x * TLN;
    int m0 = blockIdx.y * TLM;

    float acc[4][4][4];
    #pragma unroll
    for (int mt = 0; mt < 4; mt++)
        #pragma unroll
        for (int nt = 0; nt < 4; nt++)
            #pragma unroll
            for (int r = 0; r < 4; r++) acc[mt][nt][r] = 0.f;

    uint32_t aoff = (uint32_t)((wm * 64 + (lane & 15)) * SROW + (lane >> 4) * 16);
    uint32_t boff = (uint32_t)((wn * 32 + (lane & 7) + (lane >> 4) * 8) * SROW +
                               ((lane >> 3) & 1) * 16);

    // 6144 cp16 per chunk -> 12 per thread -> 4 parts of 3
    #define ISSUE_PART(k0_, buf_, part_) do {                                         \
        uint32_t stage_ = smem_base + (uint32_t)(buf_) * STAGE_BYTES;                 \
        _Pragma("unroll")                                                             \
        for (int j_ = 0; j_ < 3; j_++) {                                              \
            int v_ = tid + ((part_) * 3 + j_) * NTHR;                                 \
            int isB_ = v_ >= 4096;                                                    \
            int r_ = isB_ ? v_ - 4096 : v_;                                           \
            int p_ = isB_ ? (r_ >> 10) : (r_ >> 11);                                  \
            int rem_ = isB_ ? (r_ & 1023) : (r_ & 2047);                              \
            int row_ = rem_ >> 3;                                                     \
            int ch_ = rem_ & 7;                                                       \
            const __nv_bfloat16* s_ = isB_                                            \
                ? g_B + (size_t)p_ * BSZ + (size_t)(n0 + row_) * DIMK + (k0_) + ch_ * 8 \
                : g_A + (size_t)p_ * ASZ + (size_t)(m0 + row_) * DIMK + (k0_) + ch_ * 8; \
            uint32_t d_ = stage_ +                                                    \
                (isB_ ? (uint32_t)(B_BASE + p_ * B_SPLIT) : (uint32_t)(p_ * A_SPLIT)) \
                + (uint32_t)(row_ * SROW + ch_ * 16);                                 \
            cp16(d_, s_);                                                             \
        }                                                                             \
    } while (0)

    // prologue: chunk 0 -> buf 0
    ISSUE_PART(0, 0, 0);
    ISSUE_PART(0, 0, 1);
    ISSUE_PART(0, 0, 2);
    ISSUE_PART(0, 0, 3);
    CP_COMMIT();

    #pragma unroll 1
    for (int c = 0; c < NCHG; c++) {
        int s = c & 1;
        CP_WAIT0();
        __syncthreads();

        uint32_t sA = smem_base + (uint32_t)s * STAGE_BYTES;
        uint32_t sB = sA + B_BASE;
        int knext = (c + 1) * KC;
        bool more = (c + 1 < NCHG);

        #pragma unroll
        for (int ks = 0; ks < 4; ks++) {
            uint32_t afr[4][4];
            uint32_t bfr0[4][2], bfr1[4][2];

            // B fragments, both splits
            {
                uint32_t bd0 = sB + boff + (uint32_t)(ks * 32);
                ldsm_x4(bfr0[0][0], bfr0[0][1], bfr0[1][0], bfr0[1][1], bd0);
                ldsm_x4(bfr0[2][0], bfr0[2][1], bfr0[3][0], bfr0[3][1], bd0 + 16 * SROW);
                uint32_t bd1 = bd0 + B_SPLIT;
                ldsm_x4(bfr1[0][0], bfr1[0][1], bfr1[1][0], bfr1[1][1], bd1);
                ldsm_x4(bfr1[2][0], bfr1[2][1], bfr1[3][0], bfr1[3][1], bd1 + 16 * SROW);
            }
            // A split 0
            #pragma unroll
            for (int mt = 0; mt < 4; mt++) {
                uint32_t ad = sA + aoff + (uint32_t)(mt * 16 * SROW + ks * 32);
                ldsm_x4(afr[mt][0], afr[mt][1], afr[mt][2], afr[mt][3], ad);
            }

            // front-loaded prefetch of next chunk: parts 0,1 at ks0; 2 at ks1;
            // 3 + commit at ks2 -> full kstep (~1500cyc) before next wait
            if (more && ks == 0) ISSUE_PART(knext, s ^ 1, 0);

            #pragma unroll
            for (int mt = 0; mt < 4; mt++)
                #pragma unroll
                for (int nt = 0; nt < 4; nt++)
                    mma_bf16(acc[mt][nt], afr[mt], bfr0[nt]);   // A0*B0

            if (more) {
                if (ks == 0)      ISSUE_PART(knext, s ^ 1, 1);
                else if (ks == 1) ISSUE_PART(knext, s ^ 1, 2);
                else if (ks == 2) ISSUE_PART(knext, s ^ 1, 3);
            }

            #pragma unroll
            for (int mt = 0; mt < 4; mt++)
                #pragma unroll
                for (int nt = 0; nt < 4; nt++)
                    mma_bf16(acc[mt][nt], afr[mt], bfr1[nt]);   // A0*B1

            if (more && ks == 2) CP_COMMIT();

            // A split 1 (reuse afr regs)
            #pragma unroll
            for (int mt = 0; mt < 4; mt++) {
                uint32_t ad = sA + A_SPLIT + aoff + (uint32_t)(mt * 16 * SROW + ks * 32);
                ldsm_x4(afr[mt][0], afr[mt][1], afr[mt][2], afr[mt][3], ad);
            }
            #pragma unroll
            for (int mt = 0; mt < 4; mt++)
                #pragma unroll
                for (int nt = 0; nt < 4; nt++)
                    mma_bf16(acc[mt][nt], afr[mt], bfr0[nt]);   // A1*B0
        }
    }
    #undef ISSUE_PART

    // epilogue
    const float PI_F = 3.14159265358979323846f;
    #pragma unroll
    for (int mt = 0; mt < 4; mt++) {
        #pragma unroll
        for (int nt = 0; nt < 4; nt++) {
            int r0 = m0 + wm * 64 + mt * 16 + (lane >> 2);
            int cg = n0 + wn * 32 + nt * 8 + (lane & 3) * 2;
            #pragma unroll
            for (int hh = 0; hh < 2; hh++) {
                int m = r0 + hh * 8;
                size_t row = (size_t)m * NBP;
                #pragma unroll
                for (int e = 0; e < 2; e++) {
                    int ng = cg + e;
                    float v = acc[mt][nt][hh * 2 + e];
                    if (ng < NBINS) {
                        v += __ldg(bmag + ng);
                        v = fminf(fmaxf(v, -10.f), 10.f);
                        g_mag[row + ng] = expf(v);
                    } else {
                        int nn = ng - NBINS;     // phase bins 0..510
                        v += __ldg(bphs + nn);
                        v = fminf(fmaxf(v, -PI_F), PI_F);
                        g_frq[row + nn] = v;
                    }
                }
            }
        }
    }
}

// ---------------- phase bins 511, 512: fp32 SIMT dot ---------------------------------
__global__ __launch_bounds__(256) void extra_bins_kernel(
    const float* __restrict__ x, const float* __restrict__ Wp,
    const float* __restrict__ bp)
{
    __shared__ float w0[1024];
    __shared__ float w1[1024];
    int tid = threadIdx.x;
    for (int k = tid; k < 1024; k += 256) {
        w0[k] = Wp[(size_t)511 * DIMK + k];
        w1[k] = Wp[(size_t)512 * DIMK + k];
    }
    __syncthreads();

    int t = blockIdx.x * 256 + tid;
    int b = blockIdx.y;
    const float* xb = x + (size_t)b * DIMK * TT + t;
    float a0 = 0.f, a1 = 0.f;
    #pragma unroll 8
    for (int k = 0; k < DIMK; k++) {
        float xv = xb[(size_t)k * TT];
        a0 = fmaf(xv, w0[k], a0);
        a1 = fmaf(xv, w1[k], a1);
    }
    const float PI_F = 3.14159265358979323846f;
    size_t row = (size_t)(b * TT + t) * NBP;
    g_frq[row + 511] = fminf(fmaxf(a0 + bp[511], -PI_F), PI_F);
    g_frq[row + 512] = fminf(fmaxf(a1 + bp[512], -PI_F), PI_F);
}

// ---------------- cumsum: 3-phase segmented scan ----------------------------------------
__global__ void cumsum_seg() {
    int n = blockIdx.x * 128 + threadIdx.x;
    int b = blockIdx.y, sg = blockIdx.z;
    if (n >= NBINS) return;
    size_t base = ((size_t)b * TT + (size_t)sg * TSEG) * NBP + n;
    float acc = 0.f;
    #pragma unroll 8
    for (int t = 0; t < TSEG; t++)
        acc += g_frq[base + (size_t)t * NBP];
    g_segsum[b][sg][n] = acc;
}

__global__ void cumsum_scan() {
    int n = blockIdx.x * 128 + threadIdx.x;
    int b = blockIdx.y;
    if (n >= NBINS) return;
    float acc = 0.f;
    #pragma unroll
    for (int sg = 0; sg < NSEG; sg++) {
        float v = g_segsum[b][sg][n];
        g_segsum[b][sg][n] = acc;    // exclusive prefix
        acc += v;
    }
}

__global__ void cumsum_apply() {
    int n = blockIdx.x * 128 + threadIdx.x;
    int b = blockIdx.y, sg = blockIdx.z;
    if (n >= NBINS) return;
    float acc = g_segsum[b][sg][n];
    size_t base = ((size_t)b * TT + (size_t)sg * TSEG) * NBP + n;
    #pragma unroll 8
    for (int t = 0; t < TSEG; t++) {
        size_t o = base + (size_t)t * NBP;
        acc += g_frq[o];
        g_frq[o] = acc;
    }
}

// ---------------- frames: real irfft(1024) via 512-pt complex IFFT ---------------------
__global__ __launch_bounds__(128) void frames_kernel() {
    __shared__ float sxr[513];
    __shared__ float sxi[513];
    __shared__ float wre[512];
    __shared__ float wim[512];
    __shared__ float twr[256];
    __shared__ float twi[256];

    int f = blockIdx.x;
    int tid = threadIdx.x;
    size_t base = (size_t)f * NBP;

    for (int i = tid; i < 256; i += 128) {
        twr[i] = g_c512[i];
        twi[i] = g_s512[i];
    }
    for (int n = tid; n < 513; n += 128) {
        float mg = g_mag[base + n];
        float ph = g_frq[base + n];
        float s, c;
        sincosf(ph, &s, &c);
        float im = mg * s;
        if (n == 0 || n == 512) im = 0.f;
        sxr[n] = mg * c;
        sxi[n] = im;
    }
    __syncthreads();

    #pragma unroll
    for (int q = 0; q < 4; q++) {
        int k = tid + q * 128;
        int j = __brev((unsigned)k) >> 23;
        float x0r = sxr[j],       x0i = sxi[j];
        float x1r = sxr[512 - j], x1i = sxi[512 - j];
        float ar = x0r + x1r, ai = x0i - x1i;
        float br = x0r - x1r, bi = x0i + x1i;
        float tr = g_c1024[j], ti = g_s1024[j];
        wre[k] = ar - (tr * bi + ti * br);
        wim[k] = ai + (tr * br - ti * bi);
    }
    __syncthreads();

    #pragma unroll
    for (int p = 0; p < 4; p++) {
        int h = 1 << (2 * p);
        int lm = h - 1;
        int bi_ = ((tid >> (2 * p)) << (2 * p + 2)) | (tid & lm);
        int k1 = (tid & lm) << (8 - 2 * p);
        int k2 = k1 >> 1;

        float x0r = wre[bi_],         x0i = wim[bi_];
        float x1r = wre[bi_ + h],     x1i = wim[bi_ + h];
        float x2r = wre[bi_ + 2 * h], x2i = wim[bi_ + 2 * h];
        float x3r = wre[bi_ + 3 * h], x3i = wim[bi_ + 3 * h];

        float w1r = twr[k1], w1i = twi[k1];
        float t1r = x1r * w1r - x1i * w1i;
        float t1i = x1r * w1i + x1i * w1r;
        float a0r = x0r + t1r, a0i = x0i + t1i;
        float a1r = x0r - t1r, a1i = x0i - t1i;
        float t2r = x3r * w1r - x3i * w1i;
        float t2i = x3r * w1i + x3i * w1r;
        float a2r = x2r + t2r, a2i = x2i + t2i;
        float a3r = x2r - t2r, a3i = x2i - t2i;

        float w2r = twr[k2], w2i = twi[k2];
        float u0r = a2r * w2r - a2i * w2i;
        float u0i = a2r * w2i + a2i * w2r;
        float cr  = a3r * w2r - a3i * w2i;
        float ci  = a3r * w2i + a3i * w2r;
        float u1r = -ci, u1i = cr;

        __syncthreads();
        wre[bi_] = a0r + u0r;         wim[bi_] = a0i + u0i;
        wre[bi_ + h] = a1r + u1r;     wim[bi_ + h] = a1i + u1i;
        wre[bi_ + 2 * h] = a0r - u0r; wim[bi_ + 2 * h] = a0i - u0i;
        wre[bi_ + 3 * h] = a1r - u1r; wim[bi_ + 3 * h] = a1i - u1i;
        __syncthreads();
    }

    size_t ob = (size_t)f * NFFT;
    #pragma unroll
    for (int uu = 0; uu < 2; uu++) {
        int u = tid + uu * 128;
        float wr = twr[u], wi = twi[u];
        float ar = wre[u],       ai = wim[u];
        float br = wre[u + 256], bi = wim[u + 256];
        float tr = br * wr - bi * wi;
        float ti = br * wi + bi * wr;
        float y0r = ar + tr, y0i = ai + ti;
        float y1r = ar - tr, y1i = ai - ti;
        float2 o0 = make_float2(y0r * g_winS[2 * u], y0i * g_winS[2 * u + 1]);
        float2 o1 = make_float2(y1r * g_winS[2 * u + 512], y1i * g_winS[2 * u + 513]);
        *reinterpret_cast<float2*>(&g_frames[ob + 2 * u]) = o0;
        *reinterpret_cast<float2*>(&g_frames[ob + 2 * u + 512]) = o1;
    }
}

// ---------------- overlap-add -----------------------------------------------------------
__global__ void oa_kernel(float* __restrict__ out) {
    int idx = blockIdx.x * 256 + threadIdx.x;
    if (idx >= BATCH * OUTLEN) return;
    int b = idx / OUTLEN;
    int s = idx - b * OUTLEN;
    int p = s + NFFT / 2;

    int t1 = p >> 8;  if (t1 > TT - 1) t1 = TT - 1;
    int t0 = (p >= NFFT - HOP) ? ((p - (NFFT - HOP)) >> 8) : 0;

    float sig = 0.f, env = 0.f;
    #pragma unroll 4
    for (int t = t0; t <= t1; t++) {
        int j = p - (t << 8);
        sig += g_frames[((size_t)(b * TT + t) << 10) + j];
        env += g_win2[j];
    }
    float v = sig / env;
    out[idx] = fminf(fmaxf(v, -1.f), 1.f);
}

// ---------------- launcher ----------------------------------------------------------------
extern "C" void kernel_launch(void* const* d_in, const int* in_sizes, int n_in,
                              void* d_out, int out_size) {
    (void)in_sizes; (void)n_in; (void)out_size;
    const float* x  = (const float*)d_in[0];
    const float* Wm = (const float*)d_in[1];
    const float* bm = (const float*)d_in[2];
    const float* Wp = (const float*)d_in[3];
    const float* bp = (const float*)d_in[4];
    float* out = (float*)d_out;

    cudaFuncSetAttribute(gemm_hmma, cudaFuncAttributeMaxDynamicSharedMemorySize,
                         GEMM_SMEM);

    init_tables<<<4, 256>>>();
    split_x_kernel<<<dim3(TT / 32, DIMK / 32, BATCH), dim3(32, 8)>>>(x);
    split_w_kernel<<<NPAD, 256>>>(Wm, Wp);

    gemm_hmma<<<dim3(NPAD / TLN, MTOT / TLM), NTHR, GEMM_SMEM>>>(bm, bp);
    extra_bins_kernel<<<dim3(TT / 256, BATCH), 256>>>(x, Wp, bp);

    cumsum_seg<<<dim3(5, BATCH, NSEG), 128>>>();
    cumsum_scan<<<dim3(5, BATCH), 128>>>();
    cumsum_apply<<<dim3(5, BATCH, NSEG), 128>>>();

    frames_kernel<<<MTOT, 128>>>();
    oa_kernel<<<(BATCH * OUTLEN + 255) / 256, 256>>>(out);
}